// round 1
// baseline (speedup 1.0000x reference)
#include <cuda_runtime.h>
#include <math.h>

// Problem constants
#define B_  256
#define T_  128
#define E_  300
#define H_  512
#define G4  2048          // 4*H
#define EH  812           // E+H
#define F_  1024
#define NL  4
#define BT  32768         // B*T

// ---------------------------------------------------------------------------
// Device scratch (static; no allocations anywhere)
// ---------------------------------------------------------------------------
__device__ float g_pre[268435456];            // [4][BT][G4]  = 1.07 GB  x@Wx + b (permuted cols)
__device__ float g_Wp [NL * EH * G4];         // permuted weights, 26.6 MB
__device__ float g_bp [NL * G4];              // permuted bias
__device__ float g_h  [2][NL * B_ * H_];      // ping-pong hidden state
__device__ float g_c  [NL * B_ * H_];         // cell state
__device__ float g_rnn[B_ * G4];              // concat of final c's
__device__ float g_act[3][B_ * F_];           // MLP activations

// ---------------------------------------------------------------------------
// TF32 helpers
// ---------------------------------------------------------------------------
__device__ __forceinline__ float f2tf32(float x) {
    unsigned u;
    asm("cvt.rna.tf32.f32 %0, %1;" : "=r"(u) : "f"(x));
    return __uint_as_float(u);
}

struct GemmSmem {
    float As[2][128][20];   // padded stride 20 -> conflict-free frag loads
    float Bs[2][16][136];   // padded stride 136 -> conflict-free frag loads
};

// Stage one 128x16 A tile and 16x128 B tile into smem (tf32-rounded), K-guarded.
__device__ __forceinline__ void stage_tiles(
    const float* __restrict__ A, long lda,
    const float* __restrict__ Bm, long ldb,
    int K, long m0, long n0, GemmSmem* s, int buf, int k0)
{
    int tid = threadIdx.x;
    // A: 128 rows x 16 cols
    {
        int r = tid >> 2;
        int c = (tid & 3) * 4;
#pragma unroll
        for (int i = 0; i < 2; i++) {
            int row = r + i * 64;
            const float* p = A + (m0 + row) * lda + (k0 + c);
            float4 v;
            if (k0 + c + 3 < K) {
                v = *(const float4*)p;
            } else {
                v.x = (k0 + c + 0 < K) ? p[0] : 0.f;
                v.y = (k0 + c + 1 < K) ? p[1] : 0.f;
                v.z = (k0 + c + 2 < K) ? p[2] : 0.f;
                v.w = (k0 + c + 3 < K) ? p[3] : 0.f;
            }
            s->As[buf][row][c + 0] = f2tf32(v.x);
            s->As[buf][row][c + 1] = f2tf32(v.y);
            s->As[buf][row][c + 2] = f2tf32(v.z);
            s->As[buf][row][c + 3] = f2tf32(v.w);
        }
    }
    // B: 16 rows x 128 cols
    {
        int r  = tid >> 4;
        int cb = (tid & 15) * 8;
#pragma unroll
        for (int j = 0; j < 2; j++) {
            int c = cb + j * 4;
            float4 v;
            if (k0 + r < K) {
                v = *(const float4*)(Bm + (long)(k0 + r) * ldb + n0 + c);
            } else {
                v.x = v.y = v.z = v.w = 0.f;
            }
            s->Bs[buf][r][c + 0] = f2tf32(v.x);
            s->Bs[buf][r][c + 1] = f2tf32(v.y);
            s->Bs[buf][r][c + 2] = f2tf32(v.z);
            s->Bs[buf][r][c + 3] = f2tf32(v.w);
        }
    }
}

__device__ __forceinline__ void gemm_compute(
    GemmSmem* s, int buf, float acc[4][4][4], int wr, int wc, int g, int t4)
{
#pragma unroll
    for (int ks = 0; ks < 2; ks++) {
        int k0 = ks * 8;
        unsigned af[4][4], bf[4][2];
#pragma unroll
        for (int mi = 0; mi < 4; mi++) {
            int rb = wr * 64 + mi * 16;
            af[mi][0] = __float_as_uint(s->As[buf][rb + g    ][k0 + t4    ]);
            af[mi][1] = __float_as_uint(s->As[buf][rb + g + 8][k0 + t4    ]);
            af[mi][2] = __float_as_uint(s->As[buf][rb + g    ][k0 + t4 + 4]);
            af[mi][3] = __float_as_uint(s->As[buf][rb + g + 8][k0 + t4 + 4]);
        }
#pragma unroll
        for (int ni = 0; ni < 4; ni++) {
            int cb = wc * 32 + ni * 8;
            bf[ni][0] = __float_as_uint(s->Bs[buf][k0 + t4    ][cb + g]);
            bf[ni][1] = __float_as_uint(s->Bs[buf][k0 + t4 + 4][cb + g]);
        }
#pragma unroll
        for (int mi = 0; mi < 4; mi++)
#pragma unroll
            for (int ni = 0; ni < 4; ni++)
                asm volatile(
                    "mma.sync.aligned.m16n8k8.row.col.f32.tf32.tf32.f32 "
                    "{%0,%1,%2,%3},{%4,%5,%6,%7},{%8,%9},{%0,%1,%2,%3};"
                    : "+f"(acc[mi][ni][0]), "+f"(acc[mi][ni][1]),
                      "+f"(acc[mi][ni][2]), "+f"(acc[mi][ni][3])
                    : "r"(af[mi][0]), "r"(af[mi][1]), "r"(af[mi][2]), "r"(af[mi][3]),
                      "r"(bf[ni][0]), "r"(bf[ni][1]));
    }
}

// Full 128x128 block GEMM: acc = A[m0:m0+128, :K] @ B[:K, n0:n0+128]
__device__ __forceinline__ void gemm_main(
    const float* __restrict__ A, long lda,
    const float* __restrict__ Bm, long ldb,
    int K, long m0, long n0, GemmSmem* s, float acc[4][4][4])
{
    int lane = threadIdx.x & 31, wid = threadIdx.x >> 5;
    int wr = wid >> 2, wc = wid & 3, g = lane >> 2, t4 = lane & 3;
#pragma unroll
    for (int mi = 0; mi < 4; mi++)
#pragma unroll
        for (int ni = 0; ni < 4; ni++)
#pragma unroll
            for (int k = 0; k < 4; k++) acc[mi][ni][k] = 0.f;

    int nkt = (K + 15) >> 4;
    stage_tiles(A, lda, Bm, ldb, K, m0, n0, s, 0, 0);
    __syncthreads();
    for (int kt = 0; kt < nkt; kt++) {
        gemm_compute(s, kt & 1, acc, wr, wc, g, t4);
        if (kt + 1 < nkt)
            stage_tiles(A, lda, Bm, ldb, K, m0, n0, s, (kt + 1) & 1, (kt + 1) * 16);
        __syncthreads();
    }
}

// ---------------------------------------------------------------------------
// Kernel: zero initial states (per replay)
// ---------------------------------------------------------------------------
__global__ void k_zero()
{
    int idx = blockIdx.x * 256 + threadIdx.x;
    if (idx < NL * B_ * H_) {
        g_h[0][idx] = 0.f;
        g_c[idx]    = 0.f;
    }
}

// ---------------------------------------------------------------------------
// Kernel: permute weight/bias columns.
// New col c: nt=c>>7, wn=(c>>5)&3, gate=(c>>3)&3, r=c&7
// original col = gate*512 + (nt*32 + wn*8 + r)
// -> each warp-column strip (32 cols) holds all 4 gates of the same 8 units,
//    and each mma n-tile (8 cols) is one gate -> thread-local gate fusion.
// ---------------------------------------------------------------------------
__global__ void k_permute(
    const float* __restrict__ W0, const float* __restrict__ W1,
    const float* __restrict__ W2, const float* __restrict__ W3,
    const float* __restrict__ b0, const float* __restrict__ b1,
    const float* __restrict__ b2, const float* __restrict__ b3)
{
    long idx = (long)blockIdx.x * 256 + threadIdx.x;
    long tot = (long)NL * EH * G4;
    if (idx >= tot) return;
    int  l   = (int)(idx / ((long)EH * G4));
    long rem = idx - (long)l * EH * G4;
    int  r   = (int)(rem / G4);
    int  c   = (int)(rem - (long)r * G4);
    int nt = c >> 7, wn = (c >> 5) & 3, gate = (c >> 3) & 3, rr = c & 7;
    int orig = gate * H_ + nt * 32 + wn * 8 + rr;
    const float* W = (l == 0) ? W0 : (l == 1) ? W1 : (l == 2) ? W2 : W3;
    g_Wp[idx] = W[(long)r * G4 + orig];
    if (r == 0) {
        const float* bb = (l == 0) ? b0 : (l == 1) ? b1 : (l == 2) ? b2 : b3;
        g_bp[l * G4 + c] = bb[orig];
    }
}

// ---------------------------------------------------------------------------
// Kernel: input projection  g_pre[l] = X @ Wx_l + b_l   (permuted columns)
// grid (16, 256, 4)
// ---------------------------------------------------------------------------
__global__ __launch_bounds__(256) void k_precompute(
    const float* __restrict__ prem, const float* __restrict__ hyp)
{
    int  l  = blockIdx.z;
    long n0 = (long)blockIdx.x * 128, m0 = (long)blockIdx.y * 128;
    const float* A  = (l < 2) ? prem : hyp;
    const float* Bm = g_Wp + (long)l * EH * G4;
    __shared__ GemmSmem s;
    float acc[4][4][4];
    gemm_main(A, E_, Bm, G4, E_, m0, n0, &s, acc);

    int lane = threadIdx.x & 31, wid = threadIdx.x >> 5;
    int wr = wid >> 2, wc = wid & 3, g = lane >> 2, t4 = lane & 3;
    float* out = g_pre + (long)l * BT * G4;
    const float* bias = g_bp + l * G4;
#pragma unroll
    for (int mi = 0; mi < 4; mi++)
#pragma unroll
        for (int ni = 0; ni < 4; ni++) {
            long col = n0 + wc * 32 + ni * 8 + t4 * 2;
            float bx = bias[col], by = bias[col + 1];
#pragma unroll
            for (int h = 0; h < 2; h++) {
                long row = m0 + wr * 64 + mi * 16 + g + h * 8;
                float2 v;
                v.x = acc[mi][ni][h * 2 + 0] + bx;
                v.y = acc[mi][ni][h * 2 + 1] + by;
                *(float2*)(out + row * G4 + col) = v;
            }
        }
}

// ---------------------------------------------------------------------------
// Kernel: one LSTM timestep for all 4 LSTMs, fully fused.
// z = pre[:,t_l,:] + h_prev @ Wh ; gates thread-local via permuted layout.
// grid (16, 2, 4) = 128 blocks
// ---------------------------------------------------------------------------
__global__ __launch_bounds__(256) void k_step(int t)
{
    int  l  = blockIdx.z;
    long n0 = (long)blockIdx.x * 128, m0 = (long)blockIdx.y * 128;
    int  tl = (l & 1) ? (T_ - 1 - t) : t;
    const float* A  = g_h[t & 1] + (long)l * B_ * H_;
    const float* Bm = g_Wp + (long)l * EH * G4 + (long)E_ * G4;
    __shared__ GemmSmem s;
    float acc[4][4][4];
    gemm_main(A, H_, Bm, G4, H_, m0, n0, &s, acc);

    int lane = threadIdx.x & 31, wid = threadIdx.x >> 5;
    int wr = wid >> 2, wc = wid & 3, g = lane >> 2, t4 = lane & 3;
    const float* pre = g_pre + (long)l * BT * G4;
    float* cptr = g_c + (long)l * B_ * H_;
    float* hnew = g_h[(t + 1) & 1] + (long)l * B_ * H_;
    int nt = blockIdx.x;
#pragma unroll
    for (int mi = 0; mi < 4; mi++) {
#pragma unroll
        for (int h = 0; h < 2; h++) {
            long row  = m0 + wr * 64 + mi * 16 + g + h * 8;       // batch index
            long preb = ((long)row * T_ + tl) * G4 + n0 + wc * 32;
#pragma unroll
            for (int p = 0; p < 2; p++) {
                int r = t4 * 2 + p;
                int k = h * 2 + p;
                float zi = acc[mi][0][k] + pre[preb + 0 * 8 + r];
                float zj = acc[mi][1][k] + pre[preb + 1 * 8 + r];
                float zf = acc[mi][2][k] + pre[preb + 2 * 8 + r];
                float zo = acc[mi][3][k] + pre[preb + 3 * 8 + r];
                int  gidx = nt * 32 + wc * 8 + r;
                long ci   = row * H_ + gidx;
                float c_old = cptr[ci];
                float fg = 1.f / (1.f + expf(-(zf + 1.f)));
                float ig = 1.f / (1.f + expf(-zi));
                float og = 1.f / (1.f + expf(-zo));
                float cn = c_old * fg + ig * tanhf(zj);
                cptr[ci] = cn;
                hnew[ci] = tanhf(cn) * og;
            }
        }
    }
}

// ---------------------------------------------------------------------------
// Kernel: gather final cell states into rnn_out [B, 2048]
// ---------------------------------------------------------------------------
__global__ void k_gather()
{
    int idx = blockIdx.x * 256 + threadIdx.x;
    if (idx < B_ * G4) {
        int b = idx >> 11, kk = idx & 2047;
        int l = kk >> 9, gg = kk & 511;
        g_rnn[idx] = g_c[(long)l * B_ * H_ + (long)b * H_ + gg];
    }
}

// ---------------------------------------------------------------------------
// Kernel: dense layer  out = tanh(A @ W + b)   grid (N/128, M/128)
// a_sel: 0 = g_rnn (K=2048), 1..3 = g_act[a_sel-1]; writes g_act[o_sel]
// ---------------------------------------------------------------------------
__global__ __launch_bounds__(256) void k_dense(
    int a_sel, int K, const float* __restrict__ W, int N,
    const float* __restrict__ bias, int o_sel)
{
    long n0 = (long)blockIdx.x * 128, m0 = (long)blockIdx.y * 128;
    const float* A = (a_sel == 0) ? g_rnn : g_act[a_sel - 1];
    float* out = g_act[o_sel];
    __shared__ GemmSmem s;
    float acc[4][4][4];
    gemm_main(A, (a_sel == 0) ? G4 : F_, W, N, K, m0, n0, &s, acc);

    int lane = threadIdx.x & 31, wid = threadIdx.x >> 5;
    int wr = wid >> 2, wc = wid & 3, g = lane >> 2, t4 = lane & 3;
#pragma unroll
    for (int mi = 0; mi < 4; mi++)
#pragma unroll
        for (int ni = 0; ni < 4; ni++) {
            long col = n0 + wc * 32 + ni * 8 + t4 * 2;
            float bx = bias[col], by = bias[col + 1];
#pragma unroll
            for (int h = 0; h < 2; h++) {
                long row = m0 + wr * 64 + mi * 16 + g + h * 8;
                float2 v;
                v.x = tanhf(acc[mi][ni][h * 2 + 0] + bx);
                v.y = tanhf(acc[mi][ni][h * 2 + 1] + by);
                *(float2*)(out + row * (long)N + col) = v;
            }
        }
}

// ---------------------------------------------------------------------------
// Kernel: final logits  [256,3] = a3 @ W4 + b4   (fp32 exact, one block per row)
// ---------------------------------------------------------------------------
__global__ void k_logits(const float* __restrict__ W4,
                         const float* __restrict__ b4, float* __restrict__ out)
{
    int b = blockIdx.x, tid = threadIdx.x;
    const float* A = g_act[2] + (long)b * F_;
    float s0 = 0.f, s1 = 0.f, s2 = 0.f;
    for (int k = tid; k < F_; k += 128) {
        float a = A[k];
        s0 += a * W4[k * 3 + 0];
        s1 += a * W4[k * 3 + 1];
        s2 += a * W4[k * 3 + 2];
    }
#pragma unroll
    for (int off = 16; off; off >>= 1) {
        s0 += __shfl_down_sync(0xffffffffu, s0, off);
        s1 += __shfl_down_sync(0xffffffffu, s1, off);
        s2 += __shfl_down_sync(0xffffffffu, s2, off);
    }
    __shared__ float red[3][4];
    if ((tid & 31) == 0) {
        red[0][tid >> 5] = s0; red[1][tid >> 5] = s1; red[2][tid >> 5] = s2;
    }
    __syncthreads();
    if (tid == 0) {
        out[b * 3 + 0] = red[0][0] + red[0][1] + red[0][2] + red[0][3] + b4[0];
        out[b * 3 + 1] = red[1][0] + red[1][1] + red[1][2] + red[1][3] + b4[1];
        out[b * 3 + 2] = red[2][0] + red[2][1] + red[2][2] + red[2][3] + b4[2];
    }
}

// ---------------------------------------------------------------------------
// kernel_launch
// ---------------------------------------------------------------------------
extern "C" void kernel_launch(void* const* d_in, const int* in_sizes, int n_in,
                              void* d_out, int out_size)
{
    (void)in_sizes; (void)n_in; (void)out_size;
    const float* prem   = (const float*)d_in[0];
    const float* hyp    = (const float*)d_in[1];
    const float* W_fw_p = (const float*)d_in[2];
    const float* b_fw_p = (const float*)d_in[3];
    const float* W_bw_p = (const float*)d_in[4];
    const float* b_bw_p = (const float*)d_in[5];
    const float* W_fw_h = (const float*)d_in[6];
    const float* b_fw_h = (const float*)d_in[7];
    const float* W_bw_h = (const float*)d_in[8];
    const float* b_bw_h = (const float*)d_in[9];
    const float* W1 = (const float*)d_in[10];
    const float* b1 = (const float*)d_in[11];
    const float* W2 = (const float*)d_in[12];
    const float* b2 = (const float*)d_in[13];
    const float* W3 = (const float*)d_in[14];
    const float* b3 = (const float*)d_in[15];
    const float* W4 = (const float*)d_in[16];
    const float* b4 = (const float*)d_in[17];
    float* out = (float*)d_out;

    int nz = NL * B_ * H_;
    k_zero<<<(nz + 255) / 256, 256>>>();

    long totW = (long)NL * EH * G4;
    k_permute<<<(int)((totW + 255) / 256), 256>>>(
        W_fw_p, W_bw_p, W_fw_h, W_bw_h, b_fw_p, b_bw_p, b_fw_h, b_bw_h);

    k_precompute<<<dim3(16, 256, 4), 256>>>(prem, hyp);

    for (int t = 0; t < T_; t++)
        k_step<<<dim3(16, 2, 4), 256>>>(t);

    k_gather<<<(B_ * G4 + 255) / 256, 256>>>();

    k_dense<<<dim3(8, 2), 256>>>(0, G4, W1, F_, b1, 0);
    k_dense<<<dim3(8, 2), 256>>>(1, F_, W2, F_, b2, 1);
    k_dense<<<dim3(8, 2), 256>>>(2, F_, W3, F_, b3, 2);

    k_logits<<<B_, 128>>>(W4, b4, out);
}

// round 2
// speedup vs baseline: 1.4215x; 1.4215x over previous
#include <cuda_runtime.h>
#include <math.h>

// Problem constants
#define B_  256
#define T_  128
#define E_  300
#define H_  512
#define G4  2048          // 4*H
#define F_  1024
#define NL  4
#define BT  32768         // B*T
#define KT_STEPS 32       // 512 / 16
#define NSTAGE 4

// ---------------------------------------------------------------------------
// Device scratch (static; no allocations anywhere)
// ---------------------------------------------------------------------------
__device__ float g_pre[268435456];            // [4][B*T][G4] = 1.07 GB, natural col order
__device__ float g_h  [2][NL * B_ * H_];      // ping-pong hidden state (tf32-rounded)
__device__ float g_c  [NL * B_ * H_];         // cell state
__device__ float g_rnn[B_ * G4];              // concat of final c's
__device__ float g_act[3][B_ * F_];           // MLP activations
__device__ unsigned long long g_arrive [NL];  // cumulative barrier counters
__device__ unsigned long long g_release[NL];

// ---------------------------------------------------------------------------
// TF32 helper
// ---------------------------------------------------------------------------
__device__ __forceinline__ float f2tf32(float x) {
    unsigned u;
    asm("cvt.rna.tf32.f32 %0, %1;" : "=r"(u) : "f"(x));
    return __uint_as_float(u);
}

// ===========================================================================
// Generic 128x128 block GEMM (used by precompute + dense layers)
// ===========================================================================
struct GemmSmem {
    float As[2][128][20];
    float Bs[2][16][136];
};

__device__ __forceinline__ void stage_tiles(
    const float* __restrict__ A, long lda,
    const float* __restrict__ Bm, long ldb,
    int K, long m0, long n0, GemmSmem* s, int buf, int k0)
{
    int tid = threadIdx.x;
    {
        int r = tid >> 2;
        int c = (tid & 3) * 4;
#pragma unroll
        for (int i = 0; i < 2; i++) {
            int row = r + i * 64;
            const float* p = A + (m0 + row) * lda + (k0 + c);
            float4 v;
            if (k0 + c + 3 < K) {
                v = *(const float4*)p;
            } else {
                v.x = (k0 + c + 0 < K) ? p[0] : 0.f;
                v.y = (k0 + c + 1 < K) ? p[1] : 0.f;
                v.z = (k0 + c + 2 < K) ? p[2] : 0.f;
                v.w = (k0 + c + 3 < K) ? p[3] : 0.f;
            }
            s->As[buf][row][c + 0] = f2tf32(v.x);
            s->As[buf][row][c + 1] = f2tf32(v.y);
            s->As[buf][row][c + 2] = f2tf32(v.z);
            s->As[buf][row][c + 3] = f2tf32(v.w);
        }
    }
    {
        int r  = tid >> 4;
        int cb = (tid & 15) * 8;
#pragma unroll
        for (int j = 0; j < 2; j++) {
            int c = cb + j * 4;
            float4 v;
            if (k0 + r < K) {
                v = *(const float4*)(Bm + (long)(k0 + r) * ldb + n0 + c);
            } else {
                v.x = v.y = v.z = v.w = 0.f;
            }
            s->Bs[buf][r][c + 0] = f2tf32(v.x);
            s->Bs[buf][r][c + 1] = f2tf32(v.y);
            s->Bs[buf][r][c + 2] = f2tf32(v.z);
            s->Bs[buf][r][c + 3] = f2tf32(v.w);
        }
    }
}

__device__ __forceinline__ void gemm_compute(
    GemmSmem* s, int buf, float acc[4][4][4], int wr, int wc, int g, int t4)
{
#pragma unroll
    for (int ks = 0; ks < 2; ks++) {
        int k0 = ks * 8;
        unsigned af[4][4], bf[4][2];
#pragma unroll
        for (int mi = 0; mi < 4; mi++) {
            int rb = wr * 64 + mi * 16;
            af[mi][0] = __float_as_uint(s->As[buf][rb + g    ][k0 + t4    ]);
            af[mi][1] = __float_as_uint(s->As[buf][rb + g + 8][k0 + t4    ]);
            af[mi][2] = __float_as_uint(s->As[buf][rb + g    ][k0 + t4 + 4]);
            af[mi][3] = __float_as_uint(s->As[buf][rb + g + 8][k0 + t4 + 4]);
        }
#pragma unroll
        for (int ni = 0; ni < 4; ni++) {
            int cb = wc * 32 + ni * 8;
            bf[ni][0] = __float_as_uint(s->Bs[buf][k0 + t4    ][cb + g]);
            bf[ni][1] = __float_as_uint(s->Bs[buf][k0 + t4 + 4][cb + g]);
        }
#pragma unroll
        for (int mi = 0; mi < 4; mi++)
#pragma unroll
            for (int ni = 0; ni < 4; ni++)
                asm volatile(
                    "mma.sync.aligned.m16n8k8.row.col.f32.tf32.tf32.f32 "
                    "{%0,%1,%2,%3},{%4,%5,%6,%7},{%8,%9},{%0,%1,%2,%3};"
                    : "+f"(acc[mi][ni][0]), "+f"(acc[mi][ni][1]),
                      "+f"(acc[mi][ni][2]), "+f"(acc[mi][ni][3])
                    : "r"(af[mi][0]), "r"(af[mi][1]), "r"(af[mi][2]), "r"(af[mi][3]),
                      "r"(bf[ni][0]), "r"(bf[ni][1]));
    }
}

__device__ __forceinline__ void gemm_main(
    const float* __restrict__ A, long lda,
    const float* __restrict__ Bm, long ldb,
    int K, long m0, long n0, GemmSmem* s, float acc[4][4][4])
{
    int lane = threadIdx.x & 31, wid = threadIdx.x >> 5;
    int wr = wid >> 2, wc = wid & 3, g = lane >> 2, t4 = lane & 3;
#pragma unroll
    for (int mi = 0; mi < 4; mi++)
#pragma unroll
        for (int ni = 0; ni < 4; ni++)
#pragma unroll
            for (int k = 0; k < 4; k++) acc[mi][ni][k] = 0.f;

    int nkt = (K + 15) >> 4;
    stage_tiles(A, lda, Bm, ldb, K, m0, n0, s, 0, 0);
    __syncthreads();
    for (int kt = 0; kt < nkt; kt++) {
        gemm_compute(s, kt & 1, acc, wr, wc, g, t4);
        if (kt + 1 < nkt)
            stage_tiles(A, lda, Bm, ldb, K, m0, n0, s, (kt + 1) & 1, (kt + 1) * 16);
        __syncthreads();
    }
}

// ---------------------------------------------------------------------------
// k_zero: zero initial states (per replay)
// ---------------------------------------------------------------------------
__global__ void k_zero()
{
    int idx = blockIdx.x * 256 + threadIdx.x;
    if (idx < NL * B_ * H_) {
        g_h[0][idx] = 0.f;
        g_h[1][idx] = 0.f;
        g_c[idx]    = 0.f;
    }
}

// ---------------------------------------------------------------------------
// k_precompute: g_pre[l] = X @ Wx_l + b_l  (natural column order)
// grid (16, 256, 4)
// ---------------------------------------------------------------------------
__global__ __launch_bounds__(256) void k_precompute(
    const float* __restrict__ prem, const float* __restrict__ hyp,
    const float* __restrict__ W0, const float* __restrict__ W1,
    const float* __restrict__ W2, const float* __restrict__ W3,
    const float* __restrict__ b0, const float* __restrict__ b1,
    const float* __restrict__ b2, const float* __restrict__ b3)
{
    int  l  = blockIdx.z;
    long n0 = (long)blockIdx.x * 128, m0 = (long)blockIdx.y * 128;
    const float* A  = (l < 2) ? prem : hyp;
    const float* Wm = (l == 0) ? W0 : (l == 1) ? W1 : (l == 2) ? W2 : W3;
    const float* bb = (l == 0) ? b0 : (l == 1) ? b1 : (l == 2) ? b2 : b3;
    __shared__ GemmSmem s;
    float acc[4][4][4];
    gemm_main(A, E_, Wm, G4, E_, m0, n0, &s, acc);

    int lane = threadIdx.x & 31, wid = threadIdx.x >> 5;
    int wr = wid >> 2, wc = wid & 3, g = lane >> 2, t4 = lane & 3;
    float* out = g_pre + (long)l * BT * G4;
#pragma unroll
    for (int mi = 0; mi < 4; mi++)
#pragma unroll
        for (int ni = 0; ni < 4; ni++) {
            long col = n0 + wc * 32 + ni * 8 + t4 * 2;
            float bx = bb[col], by = bb[col + 1];
#pragma unroll
            for (int h = 0; h < 2; h++) {
                long row = m0 + wr * 64 + mi * 16 + g + h * 8;
                float2 v;
                v.x = acc[mi][ni][h * 2 + 0] + bx;
                v.y = acc[mi][ni][h * 2 + 1] + by;
                *(float2*)(out + row * G4 + col) = v;
            }
        }
}

// ===========================================================================
// Persistent recurrent kernel: all 128 timesteps for all 4 LSTMs.
// 128 blocks, 1/SM: block = (l = bid>>5, nb = bid&31) -> 16 hidden units,
// all 4 gates, full batch (m=256). Recurrent weights (512 x 64 tf32 = 128KB)
// live in smem in mma-fragment order. A (= h_prev) streamed via cp.async.
// ===========================================================================
struct StepSmem {
    float2 Wfrag[512][32];          // [kt*16 + s*8 + wc*4 + ni][lane] -> 128 KB
    float  As[NSTAGE][256][20];     // 80 KB (stride 20: conflict-free frags)
};
#define STEP_SMEM_BYTES sizeof(StepSmem)

__device__ __forceinline__ void issue_A(unsigned as_base_b, const float* hp,
                                        int kt, int tid)
{
#pragma unroll
    for (int i = 0; i < 4; i++) {
        int idx = tid + i * 256;                 // 0..1023 float4 groups
        int row = idx >> 2, c4 = (idx & 3) << 2;
        unsigned dst = as_base_b + (unsigned)(row * 20 + c4) * 4u;
        const float* src = hp + row * 512 + kt * 16 + c4;
        asm volatile("cp.async.cg.shared.global [%0], [%1], 16;"
                     :: "r"(dst), "l"(src));
    }
    asm volatile("cp.async.commit_group;");
}

__device__ __forceinline__ void step_compute_ktile(
    const StepSmem* s, int stg, int kt, float acc[4][4][4],
    int wr, int wc, int g, int t4, int lane)
{
#pragma unroll
    for (int ss = 0; ss < 2; ss++) {
        int k0 = ss * 8;
        unsigned af[4][4], bf[4][2];
#pragma unroll
        for (int mi = 0; mi < 4; mi++) {
            int rb = wr * 64 + mi * 16;
            af[mi][0] = __float_as_uint(s->As[stg][rb + g    ][k0 + t4    ]);
            af[mi][1] = __float_as_uint(s->As[stg][rb + g + 8][k0 + t4    ]);
            af[mi][2] = __float_as_uint(s->As[stg][rb + g    ][k0 + t4 + 4]);
            af[mi][3] = __float_as_uint(s->As[stg][rb + g + 8][k0 + t4 + 4]);
        }
#pragma unroll
        for (int ni = 0; ni < 4; ni++) {
            float2 w = s->Wfrag[kt * 16 + ss * 8 + wc * 4 + ni][lane];
            bf[ni][0] = __float_as_uint(w.x);
            bf[ni][1] = __float_as_uint(w.y);
        }
#pragma unroll
        for (int mi = 0; mi < 4; mi++)
#pragma unroll
            for (int ni = 0; ni < 4; ni++)
                asm volatile(
                    "mma.sync.aligned.m16n8k8.row.col.f32.tf32.tf32.f32 "
                    "{%0,%1,%2,%3},{%4,%5,%6,%7},{%8,%9},{%0,%1,%2,%3};"
                    : "+f"(acc[mi][ni][0]), "+f"(acc[mi][ni][1]),
                      "+f"(acc[mi][ni][2]), "+f"(acc[mi][ni][3])
                    : "r"(af[mi][0]), "r"(af[mi][1]), "r"(af[mi][2]), "r"(af[mi][3]),
                      "r"(bf[ni][0]), "r"(bf[ni][1]));
    }
}

__global__ __launch_bounds__(256, 1) void k_step_persist(
    const float* __restrict__ W0, const float* __restrict__ W1,
    const float* __restrict__ W2, const float* __restrict__ W3)
{
    extern __shared__ char raw[];
    StepSmem* s = (StepSmem*)raw;
    int tid = threadIdx.x, lane = tid & 31, wid = tid >> 5;
    int wr = wid >> 1, wc = wid & 1, g = lane >> 2, t4 = lane & 3;
    int bid = blockIdx.x, l = bid >> 5, nb = bid & 31;
    const float* W = (l == 0) ? W0 : (l == 1) ? W1 : (l == 2) ? W2 : W3;

    // -- one-time: stage this block's recurrent-weight slice into smem in
    //    fragment order (b0 = W[E+k][col], b1 = W[E+k+4][col]), tf32-rounded.
    for (int f = wid; f < 512; f += 8) {
        int ni = f & 3, wcf = (f >> 2) & 1, sf = (f >> 3) & 1, kt = f >> 4;
        int krow = E_ + kt * 16 + sf * 8 + t4;
        int col  = ni * H_ + nb * 16 + wcf * 8 + g;   // gate=ni, unit local
        float b0 = f2tf32(W[(long)krow * G4 + col]);
        float b1 = f2tf32(W[(long)(krow + 4) * G4 + col]);
        s->Wfrag[f][lane] = make_float2(b0, b1);
    }
    __syncthreads();

    const float* pre_l = g_pre + (long)l * BT * G4;
    float* c_l = g_c + l * B_ * H_;
    unsigned as0 = (unsigned)__cvta_generic_to_shared(&s->As[0][0][0]);
    const unsigned stage_bytes = 256u * 20u * 4u;

    for (int t = 0; t < T_; t++) {
        const float* hp = g_h[t & 1] + l * B_ * H_;
        float* hn = g_h[(t + 1) & 1] + l * B_ * H_;
        int tl = (l & 1) ? (T_ - 1 - t) : t;

        // prologue: prefetch stages 0..NSTAGE-2
#pragma unroll
        for (int p = 0; p < NSTAGE - 1; p++)
            issue_A(as0 + p * stage_bytes, hp, p, tid);

        float acc[4][4][4];
#pragma unroll
        for (int mi = 0; mi < 4; mi++)
#pragma unroll
            for (int ni = 0; ni < 4; ni++)
#pragma unroll
                for (int k = 0; k < 4; k++) acc[mi][ni][k] = 0.f;

        for (int kt = 0; kt < KT_STEPS; kt++) {
            asm volatile("cp.async.wait_group %0;" :: "n"(NSTAGE - 2));
            __syncthreads();
            step_compute_ktile(s, kt & (NSTAGE - 1), kt, acc, wr, wc, g, t4, lane);
            int nk = kt + NSTAGE - 1;
            if (nk < KT_STEPS)
                issue_A(as0 + (nk & (NSTAGE - 1)) * stage_bytes, hp, nk, tid);
            else
                asm volatile("cp.async.commit_group;");   // keep group counts aligned
        }

        // epilogue: z = acc + pre, gate math, update c / h (h tf32-rounded)
#pragma unroll
        for (int mi = 0; mi < 4; mi++) {
#pragma unroll
            for (int hh = 0; hh < 2; hh++) {
                int  row = wr * 64 + mi * 16 + g + hh * 8;     // batch index
                long pb  = ((long)row * T_ + tl) * G4;
#pragma unroll
                for (int p = 0; p < 2; p++) {
                    int u = nb * 16 + wc * 8 + t4 * 2 + p;     // hidden unit
                    int k = hh * 2 + p;
                    float zi = acc[mi][0][k] + pre_l[pb + 0 * H_ + u];
                    float zj = acc[mi][1][k] + pre_l[pb + 1 * H_ + u];
                    float zf = acc[mi][2][k] + pre_l[pb + 2 * H_ + u];
                    float zo = acc[mi][3][k] + pre_l[pb + 3 * H_ + u];
                    int  ci  = row * H_ + u;
                    float co = c_l[ci];
                    float fg = 1.f / (1.f + expf(-(zf + 1.f)));
                    float ig = 1.f / (1.f + expf(-zi));
                    float og = 1.f / (1.f + expf(-zo));
                    float cn = co * fg + ig * tanhf(zj);
                    c_l[ci] = cn;
                    hn[ci]  = f2tf32(tanhf(cn) * og);
                }
            }
        }

        // per-LSTM software barrier (32 blocks, cumulative counters)
        __threadfence();
        __syncthreads();
        if (tid == 0) {
            unsigned long long a = atomicAdd(&g_arrive[l], 1ULL) + 1ULL;
            unsigned long long want = (a + 31ULL) >> 5;
            if ((a & 31ULL) == 0ULL) {
                atomicAdd(&g_release[l], 1ULL);
            } else {
                while (*(volatile unsigned long long*)&g_release[l] < want)
                    __nanosleep(64);
            }
            __threadfence();
        }
        __syncthreads();
    }
}

// ---------------------------------------------------------------------------
// k_gather: rnn_out [B, 2048] = concat of final c's
// ---------------------------------------------------------------------------
__global__ void k_gather()
{
    int idx = blockIdx.x * 256 + threadIdx.x;
    if (idx < B_ * G4) {
        int b = idx >> 11, kk = idx & 2047;
        int l = kk >> 9, gg = kk & 511;
        g_rnn[idx] = g_c[(long)l * B_ * H_ + (long)b * H_ + gg];
    }
}

// ---------------------------------------------------------------------------
// k_dense: out = tanh(A @ W + b)
// ---------------------------------------------------------------------------
__global__ __launch_bounds__(256) void k_dense(
    int a_sel, int K, const float* __restrict__ W, int N,
    const float* __restrict__ bias, int o_sel)
{
    long n0 = (long)blockIdx.x * 128, m0 = (long)blockIdx.y * 128;
    const float* A = (a_sel == 0) ? g_rnn : g_act[a_sel - 1];
    float* out = g_act[o_sel];
    __shared__ GemmSmem s;
    float acc[4][4][4];
    gemm_main(A, (a_sel == 0) ? G4 : F_, W, N, K, m0, n0, &s, acc);

    int lane = threadIdx.x & 31, wid = threadIdx.x >> 5;
    int wr = wid >> 2, wc = wid & 3, g = lane >> 2, t4 = lane & 3;
#pragma unroll
    for (int mi = 0; mi < 4; mi++)
#pragma unroll
        for (int ni = 0; ni < 4; ni++) {
            long col = n0 + wc * 32 + ni * 8 + t4 * 2;
            float bx = bias[col], by = bias[col + 1];
#pragma unroll
            for (int h = 0; h < 2; h++) {
                long row = m0 + wr * 64 + mi * 16 + g + h * 8;
                float2 v;
                v.x = tanhf(acc[mi][ni][h * 2 + 0] + bx);
                v.y = tanhf(acc[mi][ni][h * 2 + 1] + by);
                *(float2*)(out + row * (long)N + col) = v;
            }
        }
}

// ---------------------------------------------------------------------------
// k_logits: [256,3] = a3 @ W4 + b4
// ---------------------------------------------------------------------------
__global__ void k_logits(const float* __restrict__ W4,
                         const float* __restrict__ b4, float* __restrict__ out)
{
    int b = blockIdx.x, tid = threadIdx.x;
    const float* A = g_act[2] + (long)b * F_;
    float s0 = 0.f, s1 = 0.f, s2 = 0.f;
    for (int k = tid; k < F_; k += 128) {
        float a = A[k];
        s0 += a * W4[k * 3 + 0];
        s1 += a * W4[k * 3 + 1];
        s2 += a * W4[k * 3 + 2];
    }
#pragma unroll
    for (int off = 16; off; off >>= 1) {
        s0 += __shfl_down_sync(0xffffffffu, s0, off);
        s1 += __shfl_down_sync(0xffffffffu, s1, off);
        s2 += __shfl_down_sync(0xffffffffu, s2, off);
    }
    __shared__ float red[3][4];
    if ((tid & 31) == 0) {
        red[0][tid >> 5] = s0; red[1][tid >> 5] = s1; red[2][tid >> 5] = s2;
    }
    __syncthreads();
    if (tid == 0) {
        out[b * 3 + 0] = red[0][0] + red[0][1] + red[0][2] + red[0][3] + b4[0];
        out[b * 3 + 1] = red[1][0] + red[1][1] + red[1][2] + red[1][3] + b4[1];
        out[b * 3 + 2] = red[2][0] + red[2][1] + red[2][2] + red[2][3] + b4[2];
    }
}

// ---------------------------------------------------------------------------
// kernel_launch
// ---------------------------------------------------------------------------
extern "C" void kernel_launch(void* const* d_in, const int* in_sizes, int n_in,
                              void* d_out, int out_size)
{
    (void)in_sizes; (void)n_in; (void)out_size;
    const float* prem   = (const float*)d_in[0];
    const float* hyp    = (const float*)d_in[1];
    const float* W_fw_p = (const float*)d_in[2];
    const float* b_fw_p = (const float*)d_in[3];
    const float* W_bw_p = (const float*)d_in[4];
    const float* b_bw_p = (const float*)d_in[5];
    const float* W_fw_h = (const float*)d_in[6];
    const float* b_fw_h = (const float*)d_in[7];
    const float* W_bw_h = (const float*)d_in[8];
    const float* b_bw_h = (const float*)d_in[9];
    const float* W1 = (const float*)d_in[10];
    const float* b1 = (const float*)d_in[11];
    const float* W2 = (const float*)d_in[12];
    const float* b2 = (const float*)d_in[13];
    const float* W3 = (const float*)d_in[14];
    const float* b3 = (const float*)d_in[15];
    const float* W4 = (const float*)d_in[16];
    const float* b4 = (const float*)d_in[17];
    float* out = (float*)d_out;

    cudaFuncSetAttribute(k_step_persist,
                         cudaFuncAttributeMaxDynamicSharedMemorySize,
                         (int)STEP_SMEM_BYTES);

    int nz = NL * B_ * H_;
    k_zero<<<(nz + 255) / 256, 256>>>();

    k_precompute<<<dim3(16, 256, 4), 256>>>(
        prem, hyp, W_fw_p, W_bw_p, W_fw_h, W_bw_h,
        b_fw_p, b_bw_p, b_fw_h, b_bw_h);

    k_step_persist<<<128, 256, STEP_SMEM_BYTES>>>(
        W_fw_p, W_bw_p, W_fw_h, W_bw_h);

    k_gather<<<(B_ * G4 + 255) / 256, 256>>>();

    k_dense<<<dim3(8, 2), 256>>>(0, G4, W1, F_, b1, 0);
    k_dense<<<dim3(8, 2), 256>>>(1, F_, W2, F_, b2, 1);
    k_dense<<<dim3(8, 2), 256>>>(2, F_, W3, F_, b3, 2);

    k_logits<<<B_, 128>>>(W4, b4, out);
}

// round 5
// speedup vs baseline: 1.6662x; 1.1721x over previous
#include <cuda_runtime.h>
#include <math.h>

// Problem constants
#define B_  256
#define T_  128
#define E_  300
#define H_  512
#define G4  2048          // 4*H
#define F_  1024
#define NL  4
#define BT  32768         // B*T
#define KP_ 304           // E padded to 16
#define KT_PRE 19         // 304/16
#define KT_STEPS 32       // 512/16
#define NSTAGE 4

// ---------------------------------------------------------------------------
// Device scratch (static; no allocations anywhere)
// ---------------------------------------------------------------------------
__device__ float g_pre[268435456];            // [4][B*T][G4] = 1.07 GB
__device__ float g_xt [2 * BT * KP_];         // tf32-rounded, zero-padded inputs
__device__ float g_wt [NL * KP_ * G4];        // tf32-rounded, padded input weights
__device__ float g_wh [NL * H_  * G4];        // tf32-rounded recurrent weights
__device__ float g_h  [2][NL * B_ * H_];      // ping-pong hidden state (tf32)
__device__ float g_c  [NL * B_ * H_];         // cell state
__device__ float g_rnn[B_ * G4];              // concat of final c's
__device__ float g_act[3][B_ * F_];           // MLP activations
__device__ unsigned long long g_arrive [NL];
__device__ unsigned long long g_release[NL];

__device__ __forceinline__ float f2tf32(float x) {
    unsigned u;
    asm("cvt.rna.tf32.f32 %0, %1;" : "=r"(u) : "f"(x));
    return __uint_as_float(u);
}

// ===========================================================================
// Prep kernels: one-pass tf32 rounding + padding
// ===========================================================================
__global__ void k_zero()
{
    int idx = blockIdx.x * 256 + threadIdx.x;
    if (idx < NL * B_ * H_) {
        g_h[0][idx] = 0.f;
        g_h[1][idx] = 0.f;
        g_c[idx]    = 0.f;
    }
}

__global__ void k_prep_x(const float* __restrict__ prem,
                         const float* __restrict__ hyp)
{
    long idx = (long)blockIdx.x * 256 + threadIdx.x;
    if (idx >= 2L * BT * KP_) return;
    int which = (int)(idx / ((long)BT * KP_));
    long rem  = idx - (long)which * BT * KP_;
    int row = (int)(rem / KP_), col = (int)(rem - (long)row * KP_);
    const float* x = which ? hyp : prem;
    g_xt[idx] = (col < E_) ? f2tf32(x[(long)row * E_ + col]) : 0.f;
}

__global__ void k_prep_w(
    const float* __restrict__ W0, const float* __restrict__ W1,
    const float* __restrict__ W2, const float* __restrict__ W3)
{
    long idx = (long)blockIdx.x * 256 + threadIdx.x;
    if (idx >= (long)NL * KP_ * G4) return;
    int l = (int)(idx / ((long)KP_ * G4));
    long rem = idx - (long)l * KP_ * G4;
    int r = (int)(rem / G4), c = (int)(rem - (long)r * G4);
    const float* W = (l == 0) ? W0 : (l == 1) ? W1 : (l == 2) ? W2 : W3;
    g_wt[idx] = (r < E_) ? f2tf32(W[(long)r * G4 + c]) : 0.f;
}

__global__ void k_prep_wh(
    const float* __restrict__ W0, const float* __restrict__ W1,
    const float* __restrict__ W2, const float* __restrict__ W3)
{
    long idx = (long)blockIdx.x * 256 + threadIdx.x;
    if (idx >= (long)NL * H_ * G4) return;
    int l = (int)(idx / ((long)H_ * G4));
    long rem = idx - (long)l * H_ * G4;
    int r = (int)(rem / G4), c = (int)(rem - (long)r * G4);
    const float* W = (l == 0) ? W0 : (l == 1) ? W1 : (l == 2) ? W2 : W3;
    g_wh[idx] = f2tf32(W[(long)(E_ + r) * G4 + c]);
}

// ===========================================================================
// Precompute GEMM: g_pre[l] = Xt @ Wt_l + b_l
// 128x128 tile, 4-stage cp.async, k-tile 16, no guards (padded K=304).
// ===========================================================================
#define PRE_A_STAGE (128 * 20)
#define PRE_B_STAGE (16 * 136)
#define PRE_SMEM_BYTES ((NSTAGE * PRE_A_STAGE + NSTAGE * PRE_B_STAGE) * 4)

__device__ __forceinline__ void pre_issue(
    unsigned sA, unsigned sB, const float* __restrict__ A,
    const float* __restrict__ Bw, int kt, long m0, long n0, int tid)
{
#pragma unroll
    for (int i = 0; i < 2; i++) {
        int c = tid + i * 256;
        int row = c >> 2, c4 = (c & 3) << 2;
        unsigned dst = sA + (unsigned)(row * 20 + c4) * 4u;
        const float* src = A + (m0 + row) * KP_ + kt * 16 + c4;
        asm volatile("cp.async.cg.shared.global [%0], [%1], 16;"
                     :: "r"(dst), "l"(src));
    }
#pragma unroll
    for (int i = 0; i < 2; i++) {
        int c = tid + i * 256;
        int row = c >> 5, c4 = (c & 31) << 2;
        unsigned dst = sB + (unsigned)(row * 136 + c4) * 4u;
        const float* src = Bw + (long)(kt * 16 + row) * G4 + n0 + c4;
        asm volatile("cp.async.cg.shared.global [%0], [%1], 16;"
                     :: "r"(dst), "l"(src));
    }
    asm volatile("cp.async.commit_group;");
}

__device__ __forceinline__ void pre_compute(
    const float* As, const float* Bs, float acc[4][4][4],
    int wr, int wc, int g, int t4)
{
#pragma unroll
    for (int ks = 0; ks < 2; ks++) {
        int k0 = ks * 8;
        unsigned af[4][4], bf[4][2];
#pragma unroll
        for (int mi = 0; mi < 4; mi++) {
            int rb = wr * 64 + mi * 16;
            af[mi][0] = __float_as_uint(As[(rb + g    ) * 20 + k0 + t4    ]);
            af[mi][1] = __float_as_uint(As[(rb + g + 8) * 20 + k0 + t4    ]);
            af[mi][2] = __float_as_uint(As[(rb + g    ) * 20 + k0 + t4 + 4]);
            af[mi][3] = __float_as_uint(As[(rb + g + 8) * 20 + k0 + t4 + 4]);
        }
#pragma unroll
        for (int ni = 0; ni < 4; ni++) {
            int cb = wc * 32 + ni * 8;
            bf[ni][0] = __float_as_uint(Bs[(k0 + t4    ) * 136 + cb + g]);
            bf[ni][1] = __float_as_uint(Bs[(k0 + t4 + 4) * 136 + cb + g]);
        }
#pragma unroll
        for (int mi = 0; mi < 4; mi++)
#pragma unroll
            for (int ni = 0; ni < 4; ni++)
                asm volatile(
                    "mma.sync.aligned.m16n8k8.row.col.f32.tf32.tf32.f32 "
                    "{%0,%1,%2,%3},{%4,%5,%6,%7},{%8,%9},{%0,%1,%2,%3};"
                    : "+f"(acc[mi][ni][0]), "+f"(acc[mi][ni][1]),
                      "+f"(acc[mi][ni][2]), "+f"(acc[mi][ni][3])
                    : "r"(af[mi][0]), "r"(af[mi][1]), "r"(af[mi][2]), "r"(af[mi][3]),
                      "r"(bf[ni][0]), "r"(bf[ni][1]));
    }
}

__global__ __launch_bounds__(256) void k_precompute2(
    const float* __restrict__ b0, const float* __restrict__ b1,
    const float* __restrict__ b2, const float* __restrict__ b3)
{
    extern __shared__ float smem[];
    float* As = smem;                          // [4][128][20]
    float* Bs = smem + NSTAGE * PRE_A_STAGE;   // [4][16][136]
    unsigned sAb = (unsigned)__cvta_generic_to_shared(As);
    unsigned sBb = (unsigned)__cvta_generic_to_shared(Bs);

    int tid = threadIdx.x, lane = tid & 31, wid = tid >> 5;
    int wr = wid >> 2, wc = wid & 3, g = lane >> 2, t4 = lane & 3;
    int l = blockIdx.z;
    long n0 = (long)blockIdx.x * 128, m0 = (long)blockIdx.y * 128;
    const float* A  = g_xt + (long)(l >> 1) * BT * KP_;
    const float* Bw = g_wt + (long)l * KP_ * G4;
    const float* bb = (l == 0) ? b0 : (l == 1) ? b1 : (l == 2) ? b2 : b3;

    float acc[4][4][4];
#pragma unroll
    for (int mi = 0; mi < 4; mi++)
#pragma unroll
        for (int ni = 0; ni < 4; ni++)
#pragma unroll
            for (int k = 0; k < 4; k++) acc[mi][ni][k] = 0.f;

#pragma unroll
    for (int p = 0; p < NSTAGE - 1; p++)
        pre_issue(sAb + p * PRE_A_STAGE * 4, sBb + p * PRE_B_STAGE * 4,
                  A, Bw, p, m0, n0, tid);

    for (int kt = 0; kt < KT_PRE; kt++) {
        asm volatile("cp.async.wait_group %0;" :: "n"(NSTAGE - 2));
        __syncthreads();
        int stg = kt & (NSTAGE - 1);
        pre_compute(As + stg * PRE_A_STAGE, Bs + stg * PRE_B_STAGE,
                    acc, wr, wc, g, t4);
        int nk = kt + NSTAGE - 1;
        if (nk < KT_PRE)
            pre_issue(sAb + (nk & (NSTAGE - 1)) * PRE_A_STAGE * 4,
                      sBb + (nk & (NSTAGE - 1)) * PRE_B_STAGE * 4,
                      A, Bw, nk, m0, n0, tid);
        else
            asm volatile("cp.async.commit_group;");
    }

    float* out = g_pre + (long)l * BT * G4;
#pragma unroll
    for (int mi = 0; mi < 4; mi++)
#pragma unroll
        for (int ni = 0; ni < 4; ni++) {
            long col = n0 + wc * 32 + ni * 8 + t4 * 2;
            float bx = bb[col], by = bb[col + 1];
#pragma unroll
            for (int h = 0; h < 2; h++) {
                long row = m0 + wr * 64 + mi * 16 + g + h * 8;
                float2 v;
                v.x = acc[mi][ni][h * 2 + 0] + bx;
                v.y = acc[mi][ni][h * 2 + 1] + by;
                *(float2*)(out + row * G4 + col) = v;
            }
        }
}

// ===========================================================================
// Persistent recurrent kernel (128 blocks, 1/SM).
// block = (l = bid>>5, nb = bid&31): 16 units x 4 gates, full batch M=256.
// Weights in smem in fragment order; h streamed via cp.async; pre prefetched
// into registers before the GEMM.
// ===========================================================================
struct StepSmem {
    float2 Wfrag[512][32];          // 128 KB
    float  As[NSTAGE][256][20];     // 80 KB
};
#define STEP_SMEM_BYTES sizeof(StepSmem)

__device__ __forceinline__ void issue_A(unsigned as_base_b, const float* hp,
                                        int kt, int tid)
{
#pragma unroll
    for (int i = 0; i < 4; i++) {
        int idx = tid + i * 256;
        int row = idx >> 2, c4 = (idx & 3) << 2;
        unsigned dst = as_base_b + (unsigned)(row * 20 + c4) * 4u;
        const float* src = hp + row * 512 + kt * 16 + c4;
        asm volatile("cp.async.cg.shared.global [%0], [%1], 16;"
                     :: "r"(dst), "l"(src));
    }
    asm volatile("cp.async.commit_group;");
}

__device__ __forceinline__ void step_compute_ktile(
    const StepSmem* s, int stg, int kt, float acc[4][4][4],
    int wr, int wc, int g, int t4, int lane)
{
#pragma unroll
    for (int ss = 0; ss < 2; ss++) {
        int k0 = ss * 8;
        unsigned af[4][4], bf[4][2];
#pragma unroll
        for (int mi = 0; mi < 4; mi++) {
            int rb = wr * 64 + mi * 16;
            af[mi][0] = __float_as_uint(s->As[stg][rb + g    ][k0 + t4    ]);
            af[mi][1] = __float_as_uint(s->As[stg][rb + g + 8][k0 + t4    ]);
            af[mi][2] = __float_as_uint(s->As[stg][rb + g    ][k0 + t4 + 4]);
            af[mi][3] = __float_as_uint(s->As[stg][rb + g + 8][k0 + t4 + 4]);
        }
#pragma unroll
        for (int ni = 0; ni < 4; ni++) {
            float2 w = s->Wfrag[kt * 16 + ss * 8 + wc * 4 + ni][lane];
            bf[ni][0] = __float_as_uint(w.x);
            bf[ni][1] = __float_as_uint(w.y);
        }
#pragma unroll
        for (int mi = 0; mi < 4; mi++)
#pragma unroll
            for (int ni = 0; ni < 4; ni++)
                asm volatile(
                    "mma.sync.aligned.m16n8k8.row.col.f32.tf32.tf32.f32 "
                    "{%0,%1,%2,%3},{%4,%5,%6,%7},{%8,%9},{%0,%1,%2,%3};"
                    : "+f"(acc[mi][ni][0]), "+f"(acc[mi][ni][1]),
                      "+f"(acc[mi][ni][2]), "+f"(acc[mi][ni][3])
                    : "r"(af[mi][0]), "r"(af[mi][1]), "r"(af[mi][2]), "r"(af[mi][3]),
                      "r"(bf[ni][0]), "r"(bf[ni][1]));
    }
}

__global__ __launch_bounds__(256, 1) void k_step_persist()
{
    extern __shared__ char raw[];
    StepSmem* s = (StepSmem*)raw;
    int tid = threadIdx.x, lane = tid & 31, wid = tid >> 5;
    int wr = wid >> 1, wc = wid & 1, g = lane >> 2, t4 = lane & 3;
    int bid = blockIdx.x, l = bid >> 5, nb = bid & 31;
    const float* Wh = g_wh + (long)l * H_ * G4;

    // one-time: stage recurrent-weight slice in fragment order (pre-rounded)
    for (int f = wid; f < 512; f += 8) {
        int ni = f & 3, wcf = (f >> 2) & 1, sf = (f >> 3) & 1, kt = f >> 4;
        int krow = kt * 16 + sf * 8 + t4;
        int col  = ni * H_ + nb * 16 + wcf * 8 + g;
        float b0 = Wh[(long)krow * G4 + col];
        float b1 = Wh[(long)(krow + 4) * G4 + col];
        s->Wfrag[f][lane] = make_float2(b0, b1);
    }
    __syncthreads();

    const float* pre_l = g_pre + (long)l * BT * G4;
    float* c_l = g_c + l * B_ * H_;
    unsigned as0 = (unsigned)__cvta_generic_to_shared(&s->As[0][0][0]);
    const unsigned stage_bytes = 256u * 20u * 4u;
    int u0 = nb * 16 + wc * 8 + t4 * 2;     // this thread's first hidden unit

    for (int t = 0; t < T_; t++) {
        const float* hp = g_h[t & 1] + l * B_ * H_;
        float* hn = g_h[(t + 1) & 1] + l * B_ * H_;
        int tl = (l & 1) ? (T_ - 1 - t) : t;

#pragma unroll
        for (int p = 0; p < NSTAGE - 1; p++)
            issue_A(as0 + p * stage_bytes, hp, p, tid);

        // prefetch this thread's pre values into registers (latency hidden
        // under the 32-ktile GEMM)
        float2 pr[4][2][4];
#pragma unroll
        for (int mi = 0; mi < 4; mi++)
#pragma unroll
            for (int hh = 0; hh < 2; hh++) {
                int  row = wr * 64 + mi * 16 + g + hh * 8;
                long pb  = ((long)row * T_ + tl) * G4;
#pragma unroll
                for (int gate = 0; gate < 4; gate++)
                    pr[mi][hh][gate] =
                        *(const float2*)(pre_l + pb + gate * H_ + u0);
            }

        float acc[4][4][4];
#pragma unroll
        for (int mi = 0; mi < 4; mi++)
#pragma unroll
            for (int ni = 0; ni < 4; ni++)
#pragma unroll
                for (int k = 0; k < 4; k++) acc[mi][ni][k] = 0.f;

        for (int kt = 0; kt < KT_STEPS; kt++) {
            asm volatile("cp.async.wait_group %0;" :: "n"(NSTAGE - 2));
            __syncthreads();
            step_compute_ktile(s, kt & (NSTAGE - 1), kt, acc, wr, wc, g, t4, lane);
            int nk = kt + NSTAGE - 1;
            if (nk < KT_STEPS)
                issue_A(as0 + (nk & (NSTAGE - 1)) * stage_bytes, hp, nk, tid);
            else
                asm volatile("cp.async.commit_group;");
        }

        // epilogue: gates + state update (pre already in registers)
#pragma unroll
        for (int mi = 0; mi < 4; mi++) {
#pragma unroll
            for (int hh = 0; hh < 2; hh++) {
                int row = wr * 64 + mi * 16 + g + hh * 8;
#pragma unroll
                for (int p = 0; p < 2; p++) {
                    int k = hh * 2 + p;
                    float pi = p ? pr[mi][hh][0].y : pr[mi][hh][0].x;
                    float pj = p ? pr[mi][hh][1].y : pr[mi][hh][1].x;
                    float pf = p ? pr[mi][hh][2].y : pr[mi][hh][2].x;
                    float po = p ? pr[mi][hh][3].y : pr[mi][hh][3].x;
                    float zi = acc[mi][0][k] + pi;
                    float zj = acc[mi][1][k] + pj;
                    float zf = acc[mi][2][k] + pf;
                    float zo = acc[mi][3][k] + po;
                    int  ci  = row * H_ + u0 + p;
                    float co = c_l[ci];
                    float fg = 1.f / (1.f + expf(-(zf + 1.f)));
                    float ig = 1.f / (1.f + expf(-zi));
                    float og = 1.f / (1.f + expf(-zo));
                    float cn = co * fg + ig * tanhf(zj);
                    c_l[ci] = cn;
                    hn[ci]  = f2tf32(tanhf(cn) * og);
                }
            }
        }

        // per-LSTM software barrier (32 blocks)
        __threadfence();
        __syncthreads();
        if (tid == 0) {
            unsigned long long a = atomicAdd(&g_arrive[l], 1ULL) + 1ULL;
            unsigned long long want = (a + 31ULL) >> 5;
            if ((a & 31ULL) == 0ULL) {
                atomicAdd(&g_release[l], 1ULL);
            } else {
                while (*(volatile unsigned long long*)&g_release[l] < want)
                    __nanosleep(64);
            }
            __threadfence();
        }
        __syncthreads();
    }
}

// ===========================================================================
// Tail: gather + MLP (generic 2-stage GEMM, small cost)
// ===========================================================================
struct GemmSmem {
    float As[2][128][20];
    float Bs[2][16][136];
};

__device__ __forceinline__ void stage_tiles(
    const float* __restrict__ A, long lda,
    const float* __restrict__ Bm, long ldb,
    int K, long m0, long n0, GemmSmem* s, int buf, int k0)
{
    int tid = threadIdx.x;
    {
        int r = tid >> 2;
        int c = (tid & 3) * 4;
#pragma unroll
        for (int i = 0; i < 2; i++) {
            int row = r + i * 64;
            const float* p = A + (m0 + row) * lda + (k0 + c);
            float4 v;
            if (k0 + c + 3 < K) {
                v = *(const float4*)p;
            } else {
                v.x = (k0 + c + 0 < K) ? p[0] : 0.f;
                v.y = (k0 + c + 1 < K) ? p[1] : 0.f;
                v.z = (k0 + c + 2 < K) ? p[2] : 0.f;
                v.w = (k0 + c + 3 < K) ? p[3] : 0.f;
            }
            s->As[buf][row][c + 0] = f2tf32(v.x);
            s->As[buf][row][c + 1] = f2tf32(v.y);
            s->As[buf][row][c + 2] = f2tf32(v.z);
            s->As[buf][row][c + 3] = f2tf32(v.w);
        }
    }
    {
        int r  = tid >> 4;
        int cb = (tid & 15) * 8;
#pragma unroll
        for (int j = 0; j < 2; j++) {
            int c = cb + j * 4;
            float4 v;
            if (k0 + r < K) {
                v = *(const float4*)(Bm + (long)(k0 + r) * ldb + n0 + c);
            } else {
                v.x = v.y = v.z = v.w = 0.f;
            }
            s->Bs[buf][r][c + 0] = f2tf32(v.x);
            s->Bs[buf][r][c + 1] = f2tf32(v.y);
            s->Bs[buf][r][c + 2] = f2tf32(v.z);
            s->Bs[buf][r][c + 3] = f2tf32(v.w);
        }
    }
}

__device__ __forceinline__ void gemm_main(
    const float* __restrict__ A, long lda,
    const float* __restrict__ Bm, long ldb,
    int K, long m0, long n0, GemmSmem* s, float acc[4][4][4])
{
    int lane = threadIdx.x & 31, wid = threadIdx.x >> 5;
    int wr = wid >> 2, wc = wid & 3, g = lane >> 2, t4 = lane & 3;
#pragma unroll
    for (int mi = 0; mi < 4; mi++)
#pragma unroll
        for (int ni = 0; ni < 4; ni++)
#pragma unroll
            for (int k = 0; k < 4; k++) acc[mi][ni][k] = 0.f;

    int nkt = (K + 15) >> 4;
    stage_tiles(A, lda, Bm, ldb, K, m0, n0, s, 0, 0);
    __syncthreads();
    for (int kt = 0; kt < nkt; kt++) {
        pre_compute(&s->As[kt & 1][0][0], &s->Bs[kt & 1][0][0], acc, wr, wc, g, t4);
        if (kt + 1 < nkt)
            stage_tiles(A, lda, Bm, ldb, K, m0, n0, s, (kt + 1) & 1, (kt + 1) * 16);
        __syncthreads();
    }
}

__global__ void k_gather()
{
    int idx = blockIdx.x * 256 + threadIdx.x;
    if (idx < B_ * G4) {
        int b = idx >> 11, kk = idx & 2047;
        int l = kk >> 9, gg = kk & 511;
        g_rnn[idx] = g_c[(long)l * B_ * H_ + (long)b * H_ + gg];
    }
}

__global__ __launch_bounds__(256) void k_dense(
    int a_sel, int K, const float* __restrict__ W, int N,
    const float* __restrict__ bias, int o_sel)
{
    long n0 = (long)blockIdx.x * 128, m0 = (long)blockIdx.y * 128;
    const float* A = (a_sel == 0) ? g_rnn : g_act[a_sel - 1];
    float* out = g_act[o_sel];
    __shared__ GemmSmem s;
    float acc[4][4][4];
    gemm_main(A, (a_sel == 0) ? G4 : F_, W, N, K, m0, n0, &s, acc);

    int lane = threadIdx.x & 31, wid = threadIdx.x >> 5;
    int wr = wid >> 2, wc = wid & 3, g = lane >> 2, t4 = lane & 3;
#pragma unroll
    for (int mi = 0; mi < 4; mi++)
#pragma unroll
        for (int ni = 0; ni < 4; ni++) {
            long col = n0 + wc * 32 + ni * 8 + t4 * 2;
            float bx = bias[col], by = bias[col + 1];
#pragma unroll
            for (int h = 0; h < 2; h++) {
                long row = m0 + wr * 64 + mi * 16 + g + h * 8;
                float2 v;
                v.x = tanhf(acc[mi][ni][h * 2 + 0] + bx);
                v.y = tanhf(acc[mi][ni][h * 2 + 1] + by);
                *(float2*)(out + row * (long)N + col) = v;
            }
        }
}

__global__ void k_logits(const float* __restrict__ W4,
                         const float* __restrict__ b4, float* __restrict__ out)
{
    int b = blockIdx.x, tid = threadIdx.x;
    const float* A = g_act[2] + (long)b * F_;
    float s0 = 0.f, s1 = 0.f, s2 = 0.f;
    for (int k = tid; k < F_; k += 128) {
        float a = A[k];
        s0 += a * W4[k * 3 + 0];
        s1 += a * W4[k * 3 + 1];
        s2 += a * W4[k * 3 + 2];
    }
#pragma unroll
    for (int off = 16; off; off >>= 1) {
        s0 += __shfl_down_sync(0xffffffffu, s0, off);
        s1 += __shfl_down_sync(0xffffffffu, s1, off);
        s2 += __shfl_down_sync(0xffffffffu, s2, off);
    }
    __shared__ float red[3][4];
    if ((tid & 31) == 0) {
        red[0][tid >> 5] = s0; red[1][tid >> 5] = s1; red[2][tid >> 5] = s2;
    }
    __syncthreads();
    if (tid == 0) {
        out[b * 3 + 0] = red[0][0] + red[0][1] + red[0][2] + red[0][3] + b4[0];
        out[b * 3 + 1] = red[1][0] + red[1][1] + red[1][2] + red[1][3] + b4[1];
        out[b * 3 + 2] = red[2][0] + red[2][1] + red[2][2] + red[2][3] + b4[2];
    }
}

// ---------------------------------------------------------------------------
// kernel_launch
// ---------------------------------------------------------------------------
extern "C" void kernel_launch(void* const* d_in, const int* in_sizes, int n_in,
                              void* d_out, int out_size)
{
    (void)in_sizes; (void)n_in; (void)out_size;
    const float* prem   = (const float*)d_in[0];
    const float* hyp    = (const float*)d_in[1];
    const float* W_fw_p = (const float*)d_in[2];
    const float* b_fw_p = (const float*)d_in[3];
    const float* W_bw_p = (const float*)d_in[4];
    const float* b_bw_p = (const float*)d_in[5];
    const float* W_fw_h = (const float*)d_in[6];
    const float* b_fw_h = (const float*)d_in[7];
    const float* W_bw_h = (const float*)d_in[8];
    const float* b_bw_h = (const float*)d_in[9];
    const float* W1 = (const float*)d_in[10];
    const float* b1 = (const float*)d_in[11];
    const float* W2 = (const float*)d_in[12];
    const float* b2 = (const float*)d_in[13];
    const float* W3 = (const float*)d_in[14];
    const float* b3 = (const float*)d_in[15];
    const float* W4 = (const float*)d_in[16];
    const float* b4 = (const float*)d_in[17];
    float* out = (float*)d_out;

    cudaFuncSetAttribute(k_step_persist,
                         cudaFuncAttributeMaxDynamicSharedMemorySize,
                         (int)STEP_SMEM_BYTES);
    cudaFuncSetAttribute(k_precompute2,
                         cudaFuncAttributeMaxDynamicSharedMemorySize,
                         (int)PRE_SMEM_BYTES);

    int nz = NL * B_ * H_;
    k_zero<<<(nz + 255) / 256, 256>>>();

    long nx = 2L * BT * KP_;
    k_prep_x<<<(int)((nx + 255) / 256), 256>>>(prem, hyp);
    long nw = (long)NL * KP_ * G4;
    k_prep_w<<<(int)((nw + 255) / 256), 256>>>(W_fw_p, W_bw_p, W_fw_h, W_bw_h);
    long nwh = (long)NL * H_ * G4;
    k_prep_wh<<<(int)((nwh + 255) / 256), 256>>>(W_fw_p, W_bw_p, W_fw_h, W_bw_h);

    k_precompute2<<<dim3(16, 256, 4), 256, PRE_SMEM_BYTES>>>(
        b_fw_p, b_bw_p, b_fw_h, b_bw_h);

    k_step_persist<<<128, 256, STEP_SMEM_BYTES>>>();

    k_gather<<<(B_ * G4 + 255) / 256, 256>>>();

    k_dense<<<dim3(8, 2), 256>>>(0, G4, W1, F_, b1, 0);
    k_dense<<<dim3(8, 2), 256>>>(1, F_, W2, F_, b2, 1);
    k_dense<<<dim3(8, 2), 256>>>(2, F_, W3, F_, b3, 2);

    k_logits<<<B_, 128>>>(W4, b4, out);
}

// round 8
// speedup vs baseline: 1.6671x; 1.0005x over previous
#include <cuda_runtime.h>
#include <math.h>

// Problem constants
#define B_  256
#define T_  128
#define E_  300
#define H_  512
#define G4  2048          // 4*H
#define F_  1024
#define NL  4
#define BT  32768         // B*T
#define KP_ 304           // E padded to 16
#define KT_PRE 19         // 304/16
#define KT_STEPS 32       // 512/16
#define NSTAGE 4

// ---------------------------------------------------------------------------
// Device scratch (static; no allocations anywhere)
// ---------------------------------------------------------------------------
__device__ float g_pre[268435456];            // [4][B*T][G4] = 1.07 GB
__device__ float g_xt [2 * BT * KP_];         // tf32-rounded, zero-padded inputs
__device__ float g_wt [NL * KP_ * G4];        // tf32-rounded, padded input weights
__device__ float g_wh [NL * H_  * G4];        // tf32-rounded recurrent weights
__device__ float g_h  [2][NL * B_ * H_];      // ping-pong hidden state (tf32)
__device__ float g_c  [NL * B_ * H_];         // cell state
__device__ float g_rnn[B_ * G4];              // concat of final c's
__device__ float g_act[3][B_ * F_];           // MLP activations
__device__ unsigned long long g_arrive [NL];
__device__ unsigned long long g_release[NL];

__device__ __forceinline__ float f2tf32(float x) {
    unsigned u;
    asm("cvt.rna.tf32.f32 %0, %1;" : "=r"(u) : "f"(x));
    return __uint_as_float(u);
}

// ===========================================================================
// k_zero: zero initial states (per replay)
// ===========================================================================
__global__ void k_zero()
{
    int idx = blockIdx.x * 256 + threadIdx.x;
    if (idx < NL * B_ * H_) {
        g_h[0][idx] = 0.f;
        g_h[1][idx] = 0.f;
        g_c[idx]    = 0.f;
    }
}

// ===========================================================================
// k_prep_all: one launch does all tf32 rounding + padding
//   job 1: g_xt  [2*BT*KP]   from prem/hyp
//   job 2: g_wt  [NL*KP*G4]  input-weight rows, padded
//   job 3: g_wh  [NL*H*G4]   recurrent-weight rows
// Grid sized for job 1 (largest); jobs 2+3 guarded by idx.
// ===========================================================================
__global__ void k_prep_all(
    const float* __restrict__ prem, const float* __restrict__ hyp,
    const float* __restrict__ W0, const float* __restrict__ W1,
    const float* __restrict__ W2, const float* __restrict__ W3)
{
    long idx = (long)blockIdx.x * 256 + threadIdx.x;

    if (idx < 2L * BT * KP_) {
        int which = (int)(idx / ((long)BT * KP_));
        long rem  = idx - (long)which * BT * KP_;
        int row = (int)(rem / KP_), col = (int)(rem - (long)row * KP_);
        const float* x = which ? hyp : prem;
        g_xt[idx] = (col < E_) ? f2tf32(x[(long)row * E_ + col]) : 0.f;
    }
    if (idx < (long)NL * KP_ * G4) {
        int l = (int)(idx / ((long)KP_ * G4));
        long rem = idx - (long)l * KP_ * G4;
        int r = (int)(rem / G4), c = (int)(rem - (long)r * G4);
        const float* W = (l == 0) ? W0 : (l == 1) ? W1 : (l == 2) ? W2 : W3;
        g_wt[idx] = (r < E_) ? f2tf32(W[(long)r * G4 + c]) : 0.f;
    }
    if (idx < (long)NL * H_ * G4) {
        int l = (int)(idx / ((long)H_ * G4));
        long rem = idx - (long)l * H_ * G4;
        int r = (int)(rem / G4), c = (int)(rem - (long)r * G4);
        const float* W = (l == 0) ? W0 : (l == 1) ? W1 : (l == 2) ? W2 : W3;
        g_wh[idx] = f2tf32(W[(long)(E_ + r) * G4 + c]);
    }
}

// ===========================================================================
// Precompute GEMM: g_pre[l] = Xt @ Wt_l + b_l
// 128x128 tile, 4-stage cp.async, k-tile 16, no guards (padded K=304).
// ===========================================================================
#define PRE_A_STAGE (128 * 20)
#define PRE_B_STAGE (16 * 136)
#define PRE_SMEM_BYTES ((NSTAGE * PRE_A_STAGE + NSTAGE * PRE_B_STAGE) * 4)

__device__ __forceinline__ void pre_issue(
    unsigned sA, unsigned sB, const float* __restrict__ A,
    const float* __restrict__ Bw, int kt, long m0, long n0, int tid)
{
#pragma unroll
    for (int i = 0; i < 2; i++) {
        int c = tid + i * 256;
        int row = c >> 2, c4 = (c & 3) << 2;
        unsigned dst = sA + (unsigned)(row * 20 + c4) * 4u;
        const float* src = A + (m0 + row) * KP_ + kt * 16 + c4;
        asm volatile("cp.async.cg.shared.global [%0], [%1], 16;"
                     :: "r"(dst), "l"(src));
    }
#pragma unroll
    for (int i = 0; i < 2; i++) {
        int c = tid + i * 256;
        int row = c >> 5, c4 = (c & 31) << 2;
        unsigned dst = sB + (unsigned)(row * 136 + c4) * 4u;
        const float* src = Bw + (long)(kt * 16 + row) * G4 + n0 + c4;
        asm volatile("cp.async.cg.shared.global [%0], [%1], 16;"
                     :: "r"(dst), "l"(src));
    }
    asm volatile("cp.async.commit_group;");
}

__device__ __forceinline__ void pre_compute(
    const float* As, const float* Bs, float acc[4][4][4],
    int wr, int wc, int g, int t4)
{
#pragma unroll
    for (int ks = 0; ks < 2; ks++) {
        int k0 = ks * 8;
        unsigned af[4][4], bf[4][2];
#pragma unroll
        for (int mi = 0; mi < 4; mi++) {
            int rb = wr * 64 + mi * 16;
            af[mi][0] = __float_as_uint(As[(rb + g    ) * 20 + k0 + t4    ]);
            af[mi][1] = __float_as_uint(As[(rb + g + 8) * 20 + k0 + t4    ]);
            af[mi][2] = __float_as_uint(As[(rb + g    ) * 20 + k0 + t4 + 4]);
            af[mi][3] = __float_as_uint(As[(rb + g + 8) * 20 + k0 + t4 + 4]);
        }
#pragma unroll
        for (int ni = 0; ni < 4; ni++) {
            int cb = wc * 32 + ni * 8;
            bf[ni][0] = __float_as_uint(Bs[(k0 + t4    ) * 136 + cb + g]);
            bf[ni][1] = __float_as_uint(Bs[(k0 + t4 + 4) * 136 + cb + g]);
        }
#pragma unroll
        for (int mi = 0; mi < 4; mi++)
#pragma unroll
            for (int ni = 0; ni < 4; ni++)
                asm volatile(
                    "mma.sync.aligned.m16n8k8.row.col.f32.tf32.tf32.f32 "
                    "{%0,%1,%2,%3},{%4,%5,%6,%7},{%8,%9},{%0,%1,%2,%3};"
                    : "+f"(acc[mi][ni][0]), "+f"(acc[mi][ni][1]),
                      "+f"(acc[mi][ni][2]), "+f"(acc[mi][ni][3])
                    : "r"(af[mi][0]), "r"(af[mi][1]), "r"(af[mi][2]), "r"(af[mi][3]),
                      "r"(bf[ni][0]), "r"(bf[ni][1]));
    }
}

__global__ __launch_bounds__(256) void k_precompute2(
    const float* __restrict__ b0, const float* __restrict__ b1,
    const float* __restrict__ b2, const float* __restrict__ b3)
{
    extern __shared__ float smem[];
    float* As = smem;                          // [4][128][20]
    float* Bs = smem + NSTAGE * PRE_A_STAGE;   // [4][16][136]
    unsigned sAb = (unsigned)__cvta_generic_to_shared(As);
    unsigned sBb = (unsigned)__cvta_generic_to_shared(Bs);

    int tid = threadIdx.x, lane = tid & 31, wid = tid >> 5;
    int wr = wid >> 2, wc = wid & 3, g = lane >> 2, t4 = lane & 3;
    int l = blockIdx.z;
    long n0 = (long)blockIdx.x * 128, m0 = (long)blockIdx.y * 128;
    const float* A  = g_xt + (long)(l >> 1) * BT * KP_;
    const float* Bw = g_wt + (long)l * KP_ * G4;
    const float* bb = (l == 0) ? b0 : (l == 1) ? b1 : (l == 2) ? b2 : b3;

    float acc[4][4][4];
#pragma unroll
    for (int mi = 0; mi < 4; mi++)
#pragma unroll
        for (int ni = 0; ni < 4; ni++)
#pragma unroll
            for (int k = 0; k < 4; k++) acc[mi][ni][k] = 0.f;

#pragma unroll
    for (int p = 0; p < NSTAGE - 1; p++)
        pre_issue(sAb + p * PRE_A_STAGE * 4, sBb + p * PRE_B_STAGE * 4,
                  A, Bw, p, m0, n0, tid);

    for (int kt = 0; kt < KT_PRE; kt++) {
        asm volatile("cp.async.wait_group %0;" :: "n"(NSTAGE - 2));
        __syncthreads();
        int stg = kt & (NSTAGE - 1);
        pre_compute(As + stg * PRE_A_STAGE, Bs + stg * PRE_B_STAGE,
                    acc, wr, wc, g, t4);
        int nk = kt + NSTAGE - 1;
        if (nk < KT_PRE)
            pre_issue(sAb + (nk & (NSTAGE - 1)) * PRE_A_STAGE * 4,
                      sBb + (nk & (NSTAGE - 1)) * PRE_B_STAGE * 4,
                      A, Bw, nk, m0, n0, tid);
        else
            asm volatile("cp.async.commit_group;");
    }

    float* out = g_pre + (long)l * BT * G4;
#pragma unroll
    for (int mi = 0; mi < 4; mi++)
#pragma unroll
        for (int ni = 0; ni < 4; ni++) {
            long col = n0 + wc * 32 + ni * 8 + t4 * 2;
            float bx = bb[col], by = bb[col + 1];
#pragma unroll
            for (int h = 0; h < 2; h++) {
                long row = m0 + wr * 64 + mi * 16 + g + h * 8;
                float2 v;
                v.x = acc[mi][ni][h * 2 + 0] + bx;
                v.y = acc[mi][ni][h * 2 + 1] + by;
                *(float2*)(out + row * G4 + col) = v;
            }
        }
}

// ===========================================================================
// Persistent recurrent kernel (128 blocks, 1/SM).
// block = (l = bid>>5, nb = bid&31): 16 units x 4 gates, full batch M=256.
// Weights in smem in fragment order; h streamed via cp.async; pre prefetched
// into registers before the GEMM.
// ===========================================================================
struct StepSmem {
    float2 Wfrag[512][32];          // 128 KB
    float  As[NSTAGE][256][20];     // 80 KB
};
#define STEP_SMEM_BYTES sizeof(StepSmem)

__device__ __forceinline__ void issue_A(unsigned as_base_b, const float* hp,
                                        int kt, int tid)
{
#pragma unroll
    for (int i = 0; i < 4; i++) {
        int idx = tid + i * 256;
        int row = idx >> 2, c4 = (idx & 3) << 2;
        unsigned dst = as_base_b + (unsigned)(row * 20 + c4) * 4u;
        const float* src = hp + row * 512 + kt * 16 + c4;
        asm volatile("cp.async.cg.shared.global [%0], [%1], 16;"
                     :: "r"(dst), "l"(src));
    }
    asm volatile("cp.async.commit_group;");
}

__device__ __forceinline__ void step_compute_ktile(
    const StepSmem* s, int stg, int kt, float acc[4][4][4],
    int wr, int wc, int g, int t4, int lane)
{
#pragma unroll
    for (int ss = 0; ss < 2; ss++) {
        int k0 = ss * 8;
        unsigned af[4][4], bf[4][2];
#pragma unroll
        for (int mi = 0; mi < 4; mi++) {
            int rb = wr * 64 + mi * 16;
            af[mi][0] = __float_as_uint(s->As[stg][rb + g    ][k0 + t4    ]);
            af[mi][1] = __float_as_uint(s->As[stg][rb + g + 8][k0 + t4    ]);
            af[mi][2] = __float_as_uint(s->As[stg][rb + g    ][k0 + t4 + 4]);
            af[mi][3] = __float_as_uint(s->As[stg][rb + g + 8][k0 + t4 + 4]);
        }
#pragma unroll
        for (int ni = 0; ni < 4; ni++) {
            float2 w = s->Wfrag[kt * 16 + ss * 8 + wc * 4 + ni][lane];
            bf[ni][0] = __float_as_uint(w.x);
            bf[ni][1] = __float_as_uint(w.y);
        }
#pragma unroll
        for (int mi = 0; mi < 4; mi++)
#pragma unroll
            for (int ni = 0; ni < 4; ni++)
                asm volatile(
                    "mma.sync.aligned.m16n8k8.row.col.f32.tf32.tf32.f32 "
                    "{%0,%1,%2,%3},{%4,%5,%6,%7},{%8,%9},{%0,%1,%2,%3};"
                    : "+f"(acc[mi][ni][0]), "+f"(acc[mi][ni][1]),
                      "+f"(acc[mi][ni][2]), "+f"(acc[mi][ni][3])
                    : "r"(af[mi][0]), "r"(af[mi][1]), "r"(af[mi][2]), "r"(af[mi][3]),
                      "r"(bf[ni][0]), "r"(bf[ni][1]));
    }
}

__global__ __launch_bounds__(256, 1) void k_step_persist()
{
    extern __shared__ char raw[];
    StepSmem* s = (StepSmem*)raw;
    int tid = threadIdx.x, lane = tid & 31, wid = tid >> 5;
    int wr = wid >> 1, wc = wid & 1, g = lane >> 2, t4 = lane & 3;
    int bid = blockIdx.x, l = bid >> 5, nb = bid & 31;
    const float* Wh = g_wh + (long)l * H_ * G4;

    // one-time: stage recurrent-weight slice in fragment order (pre-rounded)
    for (int f = wid; f < 512; f += 8) {
        int ni = f & 3, wcf = (f >> 2) & 1, sf = (f >> 3) & 1, kt = f >> 4;
        int krow = kt * 16 + sf * 8 + t4;
        int col  = ni * H_ + nb * 16 + wcf * 8 + g;
        float b0 = Wh[(long)krow * G4 + col];
        float b1 = Wh[(long)(krow + 4) * G4 + col];
        s->Wfrag[f][lane] = make_float2(b0, b1);
    }
    __syncthreads();

    const float* pre_l = g_pre + (long)l * BT * G4;
    float* c_l = g_c + l * B_ * H_;
    unsigned as0 = (unsigned)__cvta_generic_to_shared(&s->As[0][0][0]);
    const unsigned stage_bytes = 256u * 20u * 4u;
    int u0 = nb * 16 + wc * 8 + t4 * 2;     // this thread's first hidden unit

    for (int t = 0; t < T_; t++) {
        const float* hp = g_h[t & 1] + l * B_ * H_;
        float* hn = g_h[(t + 1) & 1] + l * B_ * H_;
        int tl = (l & 1) ? (T_ - 1 - t) : t;

#pragma unroll
        for (int p = 0; p < NSTAGE - 1; p++)
            issue_A(as0 + p * stage_bytes, hp, p, tid);

        // prefetch this thread's pre values into registers (latency hidden
        // under the 32-ktile GEMM)
        float2 pr[4][2][4];
#pragma unroll
        for (int mi = 0; mi < 4; mi++)
#pragma unroll
            for (int hh = 0; hh < 2; hh++) {
                int  row = wr * 64 + mi * 16 + g + hh * 8;
                long pb  = ((long)row * T_ + tl) * G4;
#pragma unroll
                for (int gate = 0; gate < 4; gate++)
                    pr[mi][hh][gate] =
                        *(const float2*)(pre_l + pb + gate * H_ + u0);
            }

        float acc[4][4][4];
#pragma unroll
        for (int mi = 0; mi < 4; mi++)
#pragma unroll
            for (int ni = 0; ni < 4; ni++)
#pragma unroll
                for (int k = 0; k < 4; k++) acc[mi][ni][k] = 0.f;

        for (int kt = 0; kt < KT_STEPS; kt++) {
            asm volatile("cp.async.wait_group %0;" :: "n"(NSTAGE - 2));
            __syncthreads();
            step_compute_ktile(s, kt & (NSTAGE - 1), kt, acc, wr, wc, g, t4, lane);
            int nk = kt + NSTAGE - 1;
            if (nk < KT_STEPS)
                issue_A(as0 + (nk & (NSTAGE - 1)) * stage_bytes, hp, nk, tid);
            else
                asm volatile("cp.async.commit_group;");
        }

        // epilogue: gates + state update (pre already in registers)
#pragma unroll
        for (int mi = 0; mi < 4; mi++) {
#pragma unroll
            for (int hh = 0; hh < 2; hh++) {
                int row = wr * 64 + mi * 16 + g + hh * 8;
#pragma unroll
                for (int p = 0; p < 2; p++) {
                    int k = hh * 2 + p;
                    float pi = p ? pr[mi][hh][0].y : pr[mi][hh][0].x;
                    float pj = p ? pr[mi][hh][1].y : pr[mi][hh][1].x;
                    float pf = p ? pr[mi][hh][2].y : pr[mi][hh][2].x;
                    float po = p ? pr[mi][hh][3].y : pr[mi][hh][3].x;
                    float zi = acc[mi][0][k] + pi;
                    float zj = acc[mi][1][k] + pj;
                    float zf = acc[mi][2][k] + pf;
                    float zo = acc[mi][3][k] + po;
                    int  ci  = row * H_ + u0 + p;
                    float co = c_l[ci];
                    float fg = 1.f / (1.f + expf(-(zf + 1.f)));
                    float ig = 1.f / (1.f + expf(-zi));
                    float og = 1.f / (1.f + expf(-zo));
                    float cn = co * fg + ig * tanhf(zj);
                    c_l[ci] = cn;
                    hn[ci]  = f2tf32(tanhf(cn) * og);
                }
            }
        }

        // per-LSTM software barrier (32 blocks, cumulative counters).
        // Proven construct (passed rounds 2 & 5): threadfence + atomicAdd,
        // but hot volatile spin (no nanosleep backoff).
        __threadfence();
        __syncthreads();
        if (tid == 0) {
            unsigned long long a = atomicAdd(&g_arrive[l], 1ULL) + 1ULL;
            unsigned long long want = (a + 31ULL) >> 5;
            if ((a & 31ULL) == 0ULL) {
                atomicAdd(&g_release[l], 1ULL);
            } else {
                while (*(volatile unsigned long long*)&g_release[l] < want) { }
            }
            __threadfence();
        }
        __syncthreads();
    }
}

// ===========================================================================
// Tail: gather + MLP (generic 2-stage GEMM, small cost)
// ===========================================================================
struct GemmSmem {
    float As[2][128][20];
    float Bs[2][16][136];
};

__device__ __forceinline__ void stage_tiles(
    const float* __restrict__ A, long lda,
    const float* __restrict__ Bm, long ldb,
    int K, long m0, long n0, GemmSmem* s, int buf, int k0)
{
    int tid = threadIdx.x;
    {
        int r = tid >> 2;
        int c = (tid & 3) * 4;
#pragma unroll
        for (int i = 0; i < 2; i++) {
            int row = r + i * 64;
            const float* p = A + (m0 + row) * lda + (k0 + c);
            float4 v;
            if (k0 + c + 3 < K) {
                v = *(const float4*)p;
            } else {
                v.x = (k0 + c + 0 < K) ? p[0] : 0.f;
                v.y = (k0 + c + 1 < K) ? p[1] : 0.f;
                v.z = (k0 + c + 2 < K) ? p[2] : 0.f;
                v.w = (k0 + c + 3 < K) ? p[3] : 0.f;
            }
            s->As[buf][row][c + 0] = f2tf32(v.x);
            s->As[buf][row][c + 1] = f2tf32(v.y);
            s->As[buf][row][c + 2] = f2tf32(v.z);
            s->As[buf][row][c + 3] = f2tf32(v.w);
        }
    }
    {
        int r  = tid >> 4;
        int cb = (tid & 15) * 8;
#pragma unroll
        for (int j = 0; j < 2; j++) {
            int c = cb + j * 4;
            float4 v;
            if (k0 + r < K) {
                v = *(const float4*)(Bm + (long)(k0 + r) * ldb + n0 + c);
            } else {
                v.x = v.y = v.z = v.w = 0.f;
            }
            s->Bs[buf][r][c + 0] = f2tf32(v.x);
            s->Bs[buf][r][c + 1] = f2tf32(v.y);
            s->Bs[buf][r][c + 2] = f2tf32(v.z);
            s->Bs[buf][r][c + 3] = f2tf32(v.w);
        }
    }
}

__device__ __forceinline__ void gemm_main(
    const float* __restrict__ A, long lda,
    const float* __restrict__ Bm, long ldb,
    int K, long m0, long n0, GemmSmem* s, float acc[4][4][4])
{
    int lane = threadIdx.x & 31, wid = threadIdx.x >> 5;
    int wr = wid >> 2, wc = wid & 3, g = lane >> 2, t4 = lane & 3;
#pragma unroll
    for (int mi = 0; mi < 4; mi++)
#pragma unroll
        for (int ni = 0; ni < 4; ni++)
#pragma unroll
            for (int k = 0; k < 4; k++) acc[mi][ni][k] = 0.f;

    int nkt = (K + 15) >> 4;
    stage_tiles(A, lda, Bm, ldb, K, m0, n0, s, 0, 0);
    __syncthreads();
    for (int kt = 0; kt < nkt; kt++) {
        pre_compute(&s->As[kt & 1][0][0], &s->Bs[kt & 1][0][0], acc, wr, wc, g, t4);
        if (kt + 1 < nkt)
            stage_tiles(A, lda, Bm, ldb, K, m0, n0, s, (kt + 1) & 1, (kt + 1) * 16);
        __syncthreads();
    }
}

__global__ void k_gather()
{
    int idx = blockIdx.x * 256 + threadIdx.x;
    if (idx < B_ * G4) {
        int b = idx >> 11, kk = idx & 2047;
        int l = kk >> 9, gg = kk & 511;
        g_rnn[idx] = g_c[(long)l * B_ * H_ + (long)b * H_ + gg];
    }
}

__global__ __launch_bounds__(256) void k_dense(
    int a_sel, int K, const float* __restrict__ W, int N,
    const float* __restrict__ bias, int o_sel)
{
    long n0 = (long)blockIdx.x * 128, m0 = (long)blockIdx.y * 128;
    const float* A = (a_sel == 0) ? g_rnn : g_act[a_sel - 1];
    float* out = g_act[o_sel];
    __shared__ GemmSmem s;
    float acc[4][4][4];
    gemm_main(A, (a_sel == 0) ? G4 : F_, W, N, K, m0, n0, &s, acc);

    int lane = threadIdx.x & 31, wid = threadIdx.x >> 5;
    int wr = wid >> 2, wc = wid & 3, g = lane >> 2, t4 = lane & 3;
#pragma unroll
    for (int mi = 0; mi < 4; mi++)
#pragma unroll
        for (int ni = 0; ni < 4; ni++) {
            long col = n0 + wc * 32 + ni * 8 + t4 * 2;
            float bx = bias[col], by = bias[col + 1];
#pragma unroll
            for (int h = 0; h < 2; h++) {
                long row = m0 + wr * 64 + mi * 16 + g + h * 8;
                float2 v;
                v.x = tanhf(acc[mi][ni][h * 2 + 0] + bx);
                v.y = tanhf(acc[mi][ni][h * 2 + 1] + by);
                *(float2*)(out + row * (long)N + col) = v;
            }
        }
}

__global__ void k_logits(const float* __restrict__ W4,
                         const float* __restrict__ b4, float* __restrict__ out)
{
    int b = blockIdx.x, tid = threadIdx.x;
    const float* A = g_act[2] + (long)b * F_;
    float s0 = 0.f, s1 = 0.f, s2 = 0.f;
    for (int k = tid; k < F_; k += 128) {
        float a = A[k];
        s0 += a * W4[k * 3 + 0];
        s1 += a * W4[k * 3 + 1];
        s2 += a * W4[k * 3 + 2];
    }
#pragma unroll
    for (int off = 16; off; off >>= 1) {
        s0 += __shfl_down_sync(0xffffffffu, s0, off);
        s1 += __shfl_down_sync(0xffffffffu, s1, off);
        s2 += __shfl_down_sync(0xffffffffu, s2, off);
    }
    __shared__ float red[3][4];
    if ((tid & 31) == 0) {
        red[0][tid >> 5] = s0; red[1][tid >> 5] = s1; red[2][tid >> 5] = s2;
    }
    __syncthreads();
    if (tid == 0) {
        out[b * 3 + 0] = red[0][0] + red[0][1] + red[0][2] + red[0][3] + b4[0];
        out[b * 3 + 1] = red[1][0] + red[1][1] + red[1][2] + red[1][3] + b4[1];
        out[b * 3 + 2] = red[2][0] + red[2][1] + red[2][2] + red[2][3] + b4[2];
    }
}

// ---------------------------------------------------------------------------
// kernel_launch
// ---------------------------------------------------------------------------
extern "C" void kernel_launch(void* const* d_in, const int* in_sizes, int n_in,
                              void* d_out, int out_size)
{
    (void)in_sizes; (void)n_in; (void)out_size;
    const float* prem   = (const float*)d_in[0];
    const float* hyp    = (const float*)d_in[1];
    const float* W_fw_p = (const float*)d_in[2];
    const float* b_fw_p = (const float*)d_in[3];
    const float* W_bw_p = (const float*)d_in[4];
    const float* b_bw_p = (const float*)d_in[5];
    const float* W_fw_h = (const float*)d_in[6];
    const float* b_fw_h = (const float*)d_in[7];
    const float* W_bw_h = (const float*)d_in[8];
    const float* b_bw_h = (const float*)d_in[9];
    const float* W1 = (const float*)d_in[10];
    const float* b1 = (const float*)d_in[11];
    const float* W2 = (const float*)d_in[12];
    const float* b2 = (const float*)d_in[13];
    const float* W3 = (const float*)d_in[14];
    const float* b3 = (const float*)d_in[15];
    const float* W4 = (const float*)d_in[16];
    const float* b4 = (const float*)d_in[17];
    float* out = (float*)d_out;

    cudaFuncSetAttribute(k_step_persist,
                         cudaFuncAttributeMaxDynamicSharedMemorySize,
                         (int)STEP_SMEM_BYTES);
    cudaFuncSetAttribute(k_precompute2,
                         cudaFuncAttributeMaxDynamicSharedMemorySize,
                         (int)PRE_SMEM_BYTES);

    // Launch order matters for ncu (-s/-c lands on launch index 3 = step).
    int nz = NL * B_ * H_;
    k_zero<<<(nz + 255) / 256, 256>>>();                              // 0

    long nx = 2L * BT * KP_;                                          // largest job
    k_prep_all<<<(int)((nx + 255) / 256), 256>>>(
        prem, hyp, W_fw_p, W_bw_p, W_fw_h, W_bw_h);                   // 1

    k_precompute2<<<dim3(16, 256, 4), 256, PRE_SMEM_BYTES>>>(
        b_fw_p, b_bw_p, b_fw_h, b_bw_h);                              // 2

    k_step_persist<<<128, 256, STEP_SMEM_BYTES>>>();                  // 3

    k_gather<<<(B_ * G4 + 255) / 256, 256>>>();                       // 4

    k_dense<<<dim3(8, 2), 256>>>(0, G4, W1, F_, b1, 0);               // 5
    k_dense<<<dim3(8, 2), 256>>>(1, F_, W2, F_, b2, 1);               // 6
    k_dense<<<dim3(8, 2), 256>>>(2, F_, W3, F_, b3, 2);               // 7

    k_logits<<<B_, 128>>>(W4, b4, out);                               // 8
}

// round 10
// speedup vs baseline: 2.2823x; 1.3690x over previous
#include <cuda_runtime.h>
#include <cuda_fp16.h>
#include <math.h>

// Problem constants
#define B_  256
#define T_  128
#define E_  300
#define H_  512
#define G4  2048          // 4*H
#define F_  1024
#define NL  4
#define BT  32768         // B*T
#define KP_ 304           // E padded to 16
#define KT_PRE 19         // 304/16
#define KT2  16           // recurrent: 16 stages of K=32
#define NSTAGE 4

// ---------------------------------------------------------------------------
// Device scratch (static; no allocations anywhere)
// ---------------------------------------------------------------------------
__device__ float g_pre[268435456];            // [4][B*T][G4] = 1.07 GB
__device__ float g_xt [2 * BT * KP_];         // tf32-rounded, zero-padded inputs
__device__ float g_wt [NL * KP_ * G4];        // tf32-rounded, padded input weights
__device__ float g_wh [NL * H_  * G4];        // RAW fp32 recurrent weights
__device__ __align__(256) __half g_hh[2][NL * B_ * H_];  // fp16 hidden ping-pong
__device__ float g_c  [NL * B_ * H_];         // cell state (fp32)
__device__ float g_rnn[B_ * G4];              // concat of final c's
__device__ float g_act[3][B_ * F_];           // MLP activations
__device__ unsigned long long g_arrive [NL];
__device__ unsigned long long g_release[NL];

__device__ __forceinline__ float f2tf32(float x) {
    unsigned u;
    asm("cvt.rna.tf32.f32 %0, %1;" : "=r"(u) : "f"(x));
    return __uint_as_float(u);
}

// ===========================================================================
// k_zero: zero initial states (per replay)
// ===========================================================================
__global__ void k_zero()
{
    int idx = blockIdx.x * 256 + threadIdx.x;
    if (idx < NL * B_ * H_) {
        g_hh[0][idx] = __float2half(0.f);
        g_hh[1][idx] = __float2half(0.f);
        g_c[idx]     = 0.f;
    }
}

// ===========================================================================
// k_prep_all: tf32 rounding for precompute operands; raw copy of Wh.
// ===========================================================================
__global__ void k_prep_all(
    const float* __restrict__ prem, const float* __restrict__ hyp,
    const float* __restrict__ W0, const float* __restrict__ W1,
    const float* __restrict__ W2, const float* __restrict__ W3)
{
    long idx = (long)blockIdx.x * 256 + threadIdx.x;

    if (idx < 2L * BT * KP_) {
        int which = (int)(idx / ((long)BT * KP_));
        long rem  = idx - (long)which * BT * KP_;
        int row = (int)(rem / KP_), col = (int)(rem - (long)row * KP_);
        const float* x = which ? hyp : prem;
        g_xt[idx] = (col < E_) ? f2tf32(x[(long)row * E_ + col]) : 0.f;
    }
    if (idx < (long)NL * KP_ * G4) {
        int l = (int)(idx / ((long)KP_ * G4));
        long rem = idx - (long)l * KP_ * G4;
        int r = (int)(rem / G4), c = (int)(rem - (long)r * G4);
        const float* W = (l == 0) ? W0 : (l == 1) ? W1 : (l == 2) ? W2 : W3;
        g_wt[idx] = (r < E_) ? f2tf32(W[(long)r * G4 + c]) : 0.f;
    }
    if (idx < (long)NL * H_ * G4) {
        int l = (int)(idx / ((long)H_ * G4));
        long rem = idx - (long)l * H_ * G4;
        int r = (int)(rem / G4), c = (int)(rem - (long)r * G4);
        const float* W = (l == 0) ? W0 : (l == 1) ? W1 : (l == 2) ? W2 : W3;
        g_wh[idx] = W[(long)(E_ + r) * G4 + c];   // raw; fp16-rounded in-kernel
    }
}

// ===========================================================================
// Precompute GEMM (tf32, unchanged): g_pre[l] = Xt @ Wt_l + b_l
// ===========================================================================
#define PRE_A_STAGE (128 * 20)
#define PRE_B_STAGE (16 * 136)
#define PRE_SMEM_BYTES ((NSTAGE * PRE_A_STAGE + NSTAGE * PRE_B_STAGE) * 4)

__device__ __forceinline__ void pre_issue(
    unsigned sA, unsigned sB, const float* __restrict__ A,
    const float* __restrict__ Bw, int kt, long m0, long n0, int tid)
{
#pragma unroll
    for (int i = 0; i < 2; i++) {
        int c = tid + i * 256;
        int row = c >> 2, c4 = (c & 3) << 2;
        unsigned dst = sA + (unsigned)(row * 20 + c4) * 4u;
        const float* src = A + (m0 + row) * KP_ + kt * 16 + c4;
        asm volatile("cp.async.cg.shared.global [%0], [%1], 16;"
                     :: "r"(dst), "l"(src));
    }
#pragma unroll
    for (int i = 0; i < 2; i++) {
        int c = tid + i * 256;
        int row = c >> 5, c4 = (c & 31) << 2;
        unsigned dst = sB + (unsigned)(row * 136 + c4) * 4u;
        const float* src = Bw + (long)(kt * 16 + row) * G4 + n0 + c4;
        asm volatile("cp.async.cg.shared.global [%0], [%1], 16;"
                     :: "r"(dst), "l"(src));
    }
    asm volatile("cp.async.commit_group;");
}

__device__ __forceinline__ void pre_compute(
    const float* As, const float* Bs, float acc[4][4][4],
    int wr, int wc, int g, int t4)
{
#pragma unroll
    for (int ks = 0; ks < 2; ks++) {
        int k0 = ks * 8;
        unsigned af[4][4], bf[4][2];
#pragma unroll
        for (int mi = 0; mi < 4; mi++) {
            int rb = wr * 64 + mi * 16;
            af[mi][0] = __float_as_uint(As[(rb + g    ) * 20 + k0 + t4    ]);
            af[mi][1] = __float_as_uint(As[(rb + g + 8) * 20 + k0 + t4    ]);
            af[mi][2] = __float_as_uint(As[(rb + g    ) * 20 + k0 + t4 + 4]);
            af[mi][3] = __float_as_uint(As[(rb + g + 8) * 20 + k0 + t4 + 4]);
        }
#pragma unroll
        for (int ni = 0; ni < 4; ni++) {
            int cb = wc * 32 + ni * 8;
            bf[ni][0] = __float_as_uint(Bs[(k0 + t4    ) * 136 + cb + g]);
            bf[ni][1] = __float_as_uint(Bs[(k0 + t4 + 4) * 136 + cb + g]);
        }
#pragma unroll
        for (int mi = 0; mi < 4; mi++)
#pragma unroll
            for (int ni = 0; ni < 4; ni++)
                asm volatile(
                    "mma.sync.aligned.m16n8k8.row.col.f32.tf32.tf32.f32 "
                    "{%0,%1,%2,%3},{%4,%5,%6,%7},{%8,%9},{%0,%1,%2,%3};"
                    : "+f"(acc[mi][ni][0]), "+f"(acc[mi][ni][1]),
                      "+f"(acc[mi][ni][2]), "+f"(acc[mi][ni][3])
                    : "r"(af[mi][0]), "r"(af[mi][1]), "r"(af[mi][2]), "r"(af[mi][3]),
                      "r"(bf[ni][0]), "r"(bf[ni][1]));
    }
}

__global__ __launch_bounds__(256) void k_precompute2(
    const float* __restrict__ b0, const float* __restrict__ b1,
    const float* __restrict__ b2, const float* __restrict__ b3)
{
    extern __shared__ float smem[];
    float* As = smem;
    float* Bs = smem + NSTAGE * PRE_A_STAGE;
    unsigned sAb = (unsigned)__cvta_generic_to_shared(As);
    unsigned sBb = (unsigned)__cvta_generic_to_shared(Bs);

    int tid = threadIdx.x, lane = tid & 31, wid = tid >> 5;
    int wr = wid >> 2, wc = wid & 3, g = lane >> 2, t4 = lane & 3;
    int l = blockIdx.z;
    long n0 = (long)blockIdx.x * 128, m0 = (long)blockIdx.y * 128;
    const float* A  = g_xt + (long)(l >> 1) * BT * KP_;
    const float* Bw = g_wt + (long)l * KP_ * G4;
    const float* bb = (l == 0) ? b0 : (l == 1) ? b1 : (l == 2) ? b2 : b3;

    float acc[4][4][4];
#pragma unroll
    for (int mi = 0; mi < 4; mi++)
#pragma unroll
        for (int ni = 0; ni < 4; ni++)
#pragma unroll
            for (int k = 0; k < 4; k++) acc[mi][ni][k] = 0.f;

#pragma unroll
    for (int p = 0; p < NSTAGE - 1; p++)
        pre_issue(sAb + p * PRE_A_STAGE * 4, sBb + p * PRE_B_STAGE * 4,
                  A, Bw, p, m0, n0, tid);

    for (int kt = 0; kt < KT_PRE; kt++) {
        asm volatile("cp.async.wait_group %0;" :: "n"(NSTAGE - 2));
        __syncthreads();
        int stg = kt & (NSTAGE - 1);
        pre_compute(As + stg * PRE_A_STAGE, Bs + stg * PRE_B_STAGE,
                    acc, wr, wc, g, t4);
        int nk = kt + NSTAGE - 1;
        if (nk < KT_PRE)
            pre_issue(sAb + (nk & (NSTAGE - 1)) * PRE_A_STAGE * 4,
                      sBb + (nk & (NSTAGE - 1)) * PRE_B_STAGE * 4,
                      A, Bw, nk, m0, n0, tid);
        else
            asm volatile("cp.async.commit_group;");
    }

    float* out = g_pre + (long)l * BT * G4;
#pragma unroll
    for (int mi = 0; mi < 4; mi++)
#pragma unroll
        for (int ni = 0; ni < 4; ni++) {
            long col = n0 + wc * 32 + ni * 8 + t4 * 2;
            float bx = bb[col], by = bb[col + 1];
#pragma unroll
            for (int h = 0; h < 2; h++) {
                long row = m0 + wr * 64 + mi * 16 + g + h * 8;
                float2 v;
                v.x = acc[mi][ni][h * 2 + 0] + bx;
                v.y = acc[mi][ni][h * 2 + 1] + by;
                *(float2*)(out + row * G4 + col) = v;
            }
        }
}

// ===========================================================================
// Persistent recurrent kernel (128 blocks, 1/SM) — fp16 GEMM, fp32 accum.
// block = (l = bid>>5, nb = bid&31): 16 units x 4 gates, M=256, K=512.
// Wh in smem as packed m16n8k16 B-fragments (uint2 per lane).
// h (fp16) streamed via cp.async in 16 stages of K=32 (2 mma-steps/stage).
// ===========================================================================
struct StepSmem {
    uint2  Wfrag[256][32];           // [kt*8 + wc*4 + ni][lane]  64 KB
    __half As[NSTAGE][256][40];      // 32 halves data + pad      80 KB
};
#define STEP_SMEM_BYTES sizeof(StepSmem)
#define AS_STAGE_BYTES (256 * 40 * 2)

__device__ __forceinline__ void issue_A16(unsigned as_base_b, const __half* hp,
                                          int s, int tid)
{
#pragma unroll
    for (int i = 0; i < 4; i++) {
        int c = tid + i * 256;               // 0..1023 chunks of 16B
        int row = c >> 2, ch = c & 3;
        unsigned dst = as_base_b + (unsigned)(row * 40 + ch * 8) * 2u;
        const __half* src = hp + row * 512 + s * 32 + ch * 8;
        asm volatile("cp.async.cg.shared.global [%0], [%1], 16;"
                     :: "r"(dst), "l"(src));
    }
    asm volatile("cp.async.commit_group;");
}

__device__ __forceinline__ void step_compute_stage(
    const StepSmem* s, int stg, int st, float acc[4][4][4],
    int wr, int wc, int g, int t4, int lane)
{
    const __half* As = &s->As[stg][0][0];
#pragma unroll
    for (int ks = 0; ks < 2; ks++) {
        int kh = ks * 16;
        unsigned af[4][4];
        uint2    bf[4];
#pragma unroll
        for (int mi = 0; mi < 4; mi++) {
            int r0 = (wr * 64 + mi * 16 + g) * 40;
            int r1 = r0 + 8 * 40;
            af[mi][0] = *(const unsigned*)(As + r0 + kh + 2 * t4);
            af[mi][1] = *(const unsigned*)(As + r1 + kh + 2 * t4);
            af[mi][2] = *(const unsigned*)(As + r0 + kh + 8 + 2 * t4);
            af[mi][3] = *(const unsigned*)(As + r1 + kh + 8 + 2 * t4);
        }
        int kt = st * 2 + ks;
#pragma unroll
        for (int ni = 0; ni < 4; ni++)
            bf[ni] = s->Wfrag[kt * 8 + wc * 4 + ni][lane];
#pragma unroll
        for (int mi = 0; mi < 4; mi++)
#pragma unroll
            for (int ni = 0; ni < 4; ni++)
                asm volatile(
                    "mma.sync.aligned.m16n8k16.row.col.f32.f16.f16.f32 "
                    "{%0,%1,%2,%3},{%4,%5,%6,%7},{%8,%9},{%0,%1,%2,%3};"
                    : "+f"(acc[mi][ni][0]), "+f"(acc[mi][ni][1]),
                      "+f"(acc[mi][ni][2]), "+f"(acc[mi][ni][3])
                    : "r"(af[mi][0]), "r"(af[mi][1]), "r"(af[mi][2]), "r"(af[mi][3]),
                      "r"(bf[ni].x), "r"(bf[ni].y));
    }
}

__global__ __launch_bounds__(256, 1) void k_step_persist()
{
    extern __shared__ char raw[];
    StepSmem* s = (StepSmem*)raw;
    int tid = threadIdx.x, lane = tid & 31, wid = tid >> 5;
    int wr = wid >> 1, wc = wid & 1, g = lane >> 2, t4 = lane & 3;
    int bid = blockIdx.x, l = bid >> 5, nb = bid & 31;
    const float* Wh = g_wh + (long)l * H_ * G4;

    // one-time: build fp16 B-fragments in smem (m16n8k16 layout).
    // frag f = kt*8 + wcf*4 + ni; lane -> (g = col-in-tile, t4 = k pair).
    for (int f = wid; f < 256; f += 8) {
        int kt = f >> 3, rest = f & 7, wcf = rest >> 2, ni = rest & 3;
        int col = ni * H_ + nb * 16 + wcf * 8 + g;
        int k0  = kt * 16 + 2 * t4;
        float w0 = Wh[(long)(k0    ) * G4 + col];
        float w1 = Wh[(long)(k0 + 1) * G4 + col];
        float w2 = Wh[(long)(k0 + 8) * G4 + col];
        float w3 = Wh[(long)(k0 + 9) * G4 + col];
        __half2 p0 = __floats2half2_rn(w0, w1);
        __half2 p1 = __floats2half2_rn(w2, w3);
        uint2 v;
        v.x = *(unsigned*)&p0;
        v.y = *(unsigned*)&p1;
        s->Wfrag[f][lane] = v;
    }
    __syncthreads();

    const float* pre_l = g_pre + (long)l * BT * G4;
    float* c_l = g_c + l * B_ * H_;
    unsigned as0 = (unsigned)__cvta_generic_to_shared(&s->As[0][0][0]);
    int u0 = nb * 16 + wc * 8 + t4 * 2;

    for (int t = 0; t < T_; t++) {
        const __half* hp = g_hh[t & 1] + l * B_ * H_;
        __half* hn = g_hh[(t + 1) & 1] + l * B_ * H_;
        int tl = (l & 1) ? (T_ - 1 - t) : t;

#pragma unroll
        for (int p = 0; p < NSTAGE - 1; p++)
            issue_A16(as0 + p * AS_STAGE_BYTES, hp, p, tid);

        // prefetch pre values into registers (hidden under the GEMM)
        float2 pr[4][2][4];
#pragma unroll
        for (int mi = 0; mi < 4; mi++)
#pragma unroll
            for (int hh = 0; hh < 2; hh++) {
                int  row = wr * 64 + mi * 16 + g + hh * 8;
                long pb  = ((long)row * T_ + tl) * G4;
#pragma unroll
                for (int gate = 0; gate < 4; gate++)
                    pr[mi][hh][gate] =
                        *(const float2*)(pre_l + pb + gate * H_ + u0);
            }

        float acc[4][4][4];
#pragma unroll
        for (int mi = 0; mi < 4; mi++)
#pragma unroll
            for (int ni = 0; ni < 4; ni++)
#pragma unroll
                for (int k = 0; k < 4; k++) acc[mi][ni][k] = 0.f;

        for (int st = 0; st < KT2; st++) {
            asm volatile("cp.async.wait_group %0;" :: "n"(NSTAGE - 2));
            __syncthreads();
            step_compute_stage(s, st & (NSTAGE - 1), st, acc, wr, wc, g, t4, lane);
            int nk = st + NSTAGE - 1;
            if (nk < KT2)
                issue_A16(as0 + (nk & (NSTAGE - 1)) * AS_STAGE_BYTES, hp, nk, tid);
            else
                asm volatile("cp.async.commit_group;");
        }

        // epilogue: gates + state update
#pragma unroll
        for (int mi = 0; mi < 4; mi++) {
#pragma unroll
            for (int hh = 0; hh < 2; hh++) {
                int row = wr * 64 + mi * 16 + g + hh * 8;
#pragma unroll
                for (int p = 0; p < 2; p++) {
                    int k = hh * 2 + p;
                    float pi = p ? pr[mi][hh][0].y : pr[mi][hh][0].x;
                    float pj = p ? pr[mi][hh][1].y : pr[mi][hh][1].x;
                    float pf = p ? pr[mi][hh][2].y : pr[mi][hh][2].x;
                    float po = p ? pr[mi][hh][3].y : pr[mi][hh][3].x;
                    float zi = acc[mi][0][k] + pi;
                    float zj = acc[mi][1][k] + pj;
                    float zf = acc[mi][2][k] + pf;
                    float zo = acc[mi][3][k] + po;
                    int  ci  = row * H_ + u0 + p;
                    float co = c_l[ci];
                    float fg = 1.f / (1.f + __expf(-(zf + 1.f)));
                    float ig = 1.f / (1.f + __expf(-zi));
                    float og = 1.f / (1.f + __expf(-zo));
                    float cn = co * fg + ig * tanhf(zj);
                    c_l[ci] = cn;
                    hn[ci]  = __float2half_rn(tanhf(cn) * og);
                }
            }
        }

        // per-LSTM software barrier (32 blocks) — proven construct
        __threadfence();
        __syncthreads();
        if (tid == 0) {
            unsigned long long a = atomicAdd(&g_arrive[l], 1ULL) + 1ULL;
            unsigned long long want = (a + 31ULL) >> 5;
            if ((a & 31ULL) == 0ULL) {
                atomicAdd(&g_release[l], 1ULL);
            } else {
                while (*(volatile unsigned long long*)&g_release[l] < want) { }
            }
            __threadfence();
        }
        __syncthreads();
    }
}

// ===========================================================================
// Tail: gather + MLP (tf32 2-stage GEMM, unchanged)
// ===========================================================================
struct GemmSmem {
    float As[2][128][20];
    float Bs[2][16][136];
};

__device__ __forceinline__ void stage_tiles(
    const float* __restrict__ A, long lda,
    const float* __restrict__ Bm, long ldb,
    int K, long m0, long n0, GemmSmem* s, int buf, int k0)
{
    int tid = threadIdx.x;
    {
        int r = tid >> 2;
        int c = (tid & 3) * 4;
#pragma unroll
        for (int i = 0; i < 2; i++) {
            int row = r + i * 64;
            const float* p = A + (m0 + row) * lda + (k0 + c);
            float4 v;
            if (k0 + c + 3 < K) {
                v = *(const float4*)p;
            } else {
                v.x = (k0 + c + 0 < K) ? p[0] : 0.f;
                v.y = (k0 + c + 1 < K) ? p[1] : 0.f;
                v.z = (k0 + c + 2 < K) ? p[2] : 0.f;
                v.w = (k0 + c + 3 < K) ? p[3] : 0.f;
            }
            s->As[buf][row][c + 0] = f2tf32(v.x);
            s->As[buf][row][c + 1] = f2tf32(v.y);
            s->As[buf][row][c + 2] = f2tf32(v.z);
            s->As[buf][row][c + 3] = f2tf32(v.w);
        }
    }
    {
        int r  = tid >> 4;
        int cb = (tid & 15) * 8;
#pragma unroll
        for (int j = 0; j < 2; j++) {
            int c = cb + j * 4;
            float4 v;
            if (k0 + r < K) {
                v = *(const float4*)(Bm + (long)(k0 + r) * ldb + n0 + c);
            } else {
                v.x = v.y = v.z = v.w = 0.f;
            }
            s->Bs[buf][r][c + 0] = f2tf32(v.x);
            s->Bs[buf][r][c + 1] = f2tf32(v.y);
            s->Bs[buf][r][c + 2] = f2tf32(v.z);
            s->Bs[buf][r][c + 3] = f2tf32(v.w);
        }
    }
}

__device__ __forceinline__ void gemm_main(
    const float* __restrict__ A, long lda,
    const float* __restrict__ Bm, long ldb,
    int K, long m0, long n0, GemmSmem* s, float acc[4][4][4])
{
    int lane = threadIdx.x & 31, wid = threadIdx.x >> 5;
    int wr = wid >> 2, wc = wid & 3, g = lane >> 2, t4 = lane & 3;
#pragma unroll
    for (int mi = 0; mi < 4; mi++)
#pragma unroll
        for (int ni = 0; ni < 4; ni++)
#pragma unroll
            for (int k = 0; k < 4; k++) acc[mi][ni][k] = 0.f;

    int nkt = (K + 15) >> 4;
    stage_tiles(A, lda, Bm, ldb, K, m0, n0, s, 0, 0);
    __syncthreads();
    for (int kt = 0; kt < nkt; kt++) {
        pre_compute(&s->As[kt & 1][0][0], &s->Bs[kt & 1][0][0], acc, wr, wc, g, t4);
        if (kt + 1 < nkt)
            stage_tiles(A, lda, Bm, ldb, K, m0, n0, s, (kt + 1) & 1, (kt + 1) * 16);
        __syncthreads();
    }
}

__global__ void k_gather()
{
    int idx = blockIdx.x * 256 + threadIdx.x;
    if (idx < B_ * G4) {
        int b = idx >> 11, kk = idx & 2047;
        int l = kk >> 9, gg = kk & 511;
        g_rnn[idx] = g_c[(long)l * B_ * H_ + (long)b * H_ + gg];
    }
}

__global__ __launch_bounds__(256) void k_dense(
    int a_sel, int K, const float* __restrict__ W, int N,
    const float* __restrict__ bias, int o_sel)
{
    long n0 = (long)blockIdx.x * 128, m0 = (long)blockIdx.y * 128;
    const float* A = (a_sel == 0) ? g_rnn : g_act[a_sel - 1];
    float* out = g_act[o_sel];
    __shared__ GemmSmem s;
    float acc[4][4][4];
    gemm_main(A, (a_sel == 0) ? G4 : F_, W, N, K, m0, n0, &s, acc);

    int lane = threadIdx.x & 31, wid = threadIdx.x >> 5;
    int wr = wid >> 2, wc = wid & 3, g = lane >> 2, t4 = lane & 3;
#pragma unroll
    for (int mi = 0; mi < 4; mi++)
#pragma unroll
        for (int ni = 0; ni < 4; ni++) {
            long col = n0 + wc * 32 + ni * 8 + t4 * 2;
            float bx = bias[col], by = bias[col + 1];
#pragma unroll
            for (int h = 0; h < 2; h++) {
                long row = m0 + wr * 64 + mi * 16 + g + h * 8;
                float2 v;
                v.x = tanhf(acc[mi][ni][h * 2 + 0] + bx);
                v.y = tanhf(acc[mi][ni][h * 2 + 1] + by);
                *(float2*)(out + row * (long)N + col) = v;
            }
        }
}

__global__ void k_logits(const float* __restrict__ W4,
                         const float* __restrict__ b4, float* __restrict__ out)
{
    int b = blockIdx.x, tid = threadIdx.x;
    const float* A = g_act[2] + (long)b * F_;
    float s0 = 0.f, s1 = 0.f, s2 = 0.f;
    for (int k = tid; k < F_; k += 128) {
        float a = A[k];
        s0 += a * W4[k * 3 + 0];
        s1 += a * W4[k * 3 + 1];
        s2 += a * W4[k * 3 + 2];
    }
#pragma unroll
    for (int off = 16; off; off >>= 1) {
        s0 += __shfl_down_sync(0xffffffffu, s0, off);
        s1 += __shfl_down_sync(0xffffffffu, s1, off);
        s2 += __shfl_down_sync(0xffffffffu, s2, off);
    }
    __shared__ float red[3][4];
    if ((tid & 31) == 0) {
        red[0][tid >> 5] = s0; red[1][tid >> 5] = s1; red[2][tid >> 5] = s2;
    }
    __syncthreads();
    if (tid == 0) {
        out[b * 3 + 0] = red[0][0] + red[0][1] + red[0][2] + red[0][3] + b4[0];
        out[b * 3 + 1] = red[1][0] + red[1][1] + red[1][2] + red[1][3] + b4[1];
        out[b * 3 + 2] = red[2][0] + red[2][1] + red[2][2] + red[2][3] + b4[2];
    }
}

// ---------------------------------------------------------------------------
// kernel_launch
// ---------------------------------------------------------------------------
extern "C" void kernel_launch(void* const* d_in, const int* in_sizes, int n_in,
                              void* d_out, int out_size)
{
    (void)in_sizes; (void)n_in; (void)out_size;
    const float* prem   = (const float*)d_in[0];
    const float* hyp    = (const float*)d_in[1];
    const float* W_fw_p = (const float*)d_in[2];
    const float* b_fw_p = (const float*)d_in[3];
    const float* W_bw_p = (const float*)d_in[4];
    const float* b_bw_p = (const float*)d_in[5];
    const float* W_fw_h = (const float*)d_in[6];
    const float* b_fw_h = (const float*)d_in[7];
    const float* W_bw_h = (const float*)d_in[8];
    const float* b_bw_h = (const float*)d_in[9];
    const float* W1 = (const float*)d_in[10];
    const float* b1 = (const float*)d_in[11];
    const float* W2 = (const float*)d_in[12];
    const float* b2 = (const float*)d_in[13];
    const float* W3 = (const float*)d_in[14];
    const float* b3 = (const float*)d_in[15];
    const float* W4 = (const float*)d_in[16];
    const float* b4 = (const float*)d_in[17];
    float* out = (float*)d_out;

    cudaFuncSetAttribute(k_step_persist,
                         cudaFuncAttributeMaxDynamicSharedMemorySize,
                         (int)STEP_SMEM_BYTES);
    cudaFuncSetAttribute(k_precompute2,
                         cudaFuncAttributeMaxDynamicSharedMemorySize,
                         (int)PRE_SMEM_BYTES);

    // Launch order matters for ncu (capture lands on launch index 3 = step).
    int nz = NL * B_ * H_;
    k_zero<<<(nz + 255) / 256, 256>>>();                              // 0

    long nx = 2L * BT * KP_;
    k_prep_all<<<(int)((nx + 255) / 256), 256>>>(
        prem, hyp, W_fw_p, W_bw_p, W_fw_h, W_bw_h);                   // 1

    k_precompute2<<<dim3(16, 256, 4), 256, PRE_SMEM_BYTES>>>(
        b_fw_p, b_bw_p, b_fw_h, b_bw_h);                              // 2

    k_step_persist<<<128, 256, STEP_SMEM_BYTES>>>();                  // 3

    k_gather<<<(B_ * G4 + 255) / 256, 256>>>();                       // 4

    k_dense<<<dim3(8, 2), 256>>>(0, G4, W1, F_, b1, 0);               // 5
    k_dense<<<dim3(8, 2), 256>>>(1, F_, W2, F_, b2, 1);               // 6
    k_dense<<<dim3(8, 2), 256>>>(2, F_, W3, F_, b3, 2);               // 7

    k_logits<<<B_, 128>>>(W4, b4, out);                               // 8
}

// round 11
// speedup vs baseline: 2.4825x; 1.0877x over previous
#include <cuda_runtime.h>
#include <cuda_fp16.h>
#include <math.h>

// Problem constants
#define B_  256
#define T_  128
#define E_  300
#define H_  512
#define G4  2048          // 4*H
#define F_  1024
#define NL  4
#define BT  32768         // B*T
#define KP_ 304           // E padded to 16
#define KT_PRE 19         // 304/16
#define KT2  8            // recurrent: 8 stages of K=64
#define NSTAGE 4

// ---------------------------------------------------------------------------
// Device scratch (static; no allocations anywhere)
// ---------------------------------------------------------------------------
__device__ float g_pre[268435456];            // [4][B*T][G4] = 1.07 GB
__device__ float g_xt [2 * BT * KP_];         // tf32-rounded, zero-padded inputs
__device__ float g_wt [NL * KP_ * G4];        // tf32-rounded, padded input weights
__device__ float g_wh [NL * H_  * G4];        // RAW fp32 recurrent weights
__device__ __align__(256) __half g_hh[2][NL * B_ * H_];  // fp16 hidden ping-pong
__device__ float g_c  [NL * B_ * H_];         // cell state (final only)
__device__ float g_rnn[B_ * G4];              // concat of final c's
__device__ float g_act[3][B_ * F_];           // MLP activations
__device__ unsigned long long g_arrive [NL];
__device__ unsigned long long g_release[NL];

__device__ __forceinline__ float f2tf32(float x) {
    unsigned u;
    asm("cvt.rna.tf32.f32 %0, %1;" : "=r"(u) : "f"(x));
    return __uint_as_float(u);
}

// ===========================================================================
// k_zero: zero initial states (per replay)
// ===========================================================================
__global__ void k_zero()
{
    int idx = blockIdx.x * 256 + threadIdx.x;
    if (idx < NL * B_ * H_) {
        g_hh[0][idx] = __float2half(0.f);
        g_hh[1][idx] = __float2half(0.f);
    }
}

// ===========================================================================
// k_prep_all: tf32 rounding for precompute operands; raw copy of Wh.
// ===========================================================================
__global__ void k_prep_all(
    const float* __restrict__ prem, const float* __restrict__ hyp,
    const float* __restrict__ W0, const float* __restrict__ W1,
    const float* __restrict__ W2, const float* __restrict__ W3)
{
    long idx = (long)blockIdx.x * 256 + threadIdx.x;

    if (idx < 2L * BT * KP_) {
        int which = (int)(idx / ((long)BT * KP_));
        long rem  = idx - (long)which * BT * KP_;
        int row = (int)(rem / KP_), col = (int)(rem - (long)row * KP_);
        const float* x = which ? hyp : prem;
        g_xt[idx] = (col < E_) ? f2tf32(x[(long)row * E_ + col]) : 0.f;
    }
    if (idx < (long)NL * KP_ * G4) {
        int l = (int)(idx / ((long)KP_ * G4));
        long rem = idx - (long)l * KP_ * G4;
        int r = (int)(rem / G4), c = (int)(rem - (long)r * G4);
        const float* W = (l == 0) ? W0 : (l == 1) ? W1 : (l == 2) ? W2 : W3;
        g_wt[idx] = (r < E_) ? f2tf32(W[(long)r * G4 + c]) : 0.f;
    }
    if (idx < (long)NL * H_ * G4) {
        int l = (int)(idx / ((long)H_ * G4));
        long rem = idx - (long)l * H_ * G4;
        int r = (int)(rem / G4), c = (int)(rem - (long)r * G4);
        const float* W = (l == 0) ? W0 : (l == 1) ? W1 : (l == 2) ? W2 : W3;
        g_wh[idx] = W[(long)(E_ + r) * G4 + c];   // raw; fp16-rounded in-kernel
    }
}

// ===========================================================================
// Precompute GEMM (tf32, unchanged): g_pre[l] = Xt @ Wt_l + b_l
// ===========================================================================
#define PRE_A_STAGE (128 * 20)
#define PRE_B_STAGE (16 * 136)
#define PRE_SMEM_BYTES ((NSTAGE * PRE_A_STAGE + NSTAGE * PRE_B_STAGE) * 4)

__device__ __forceinline__ void pre_issue(
    unsigned sA, unsigned sB, const float* __restrict__ A,
    const float* __restrict__ Bw, int kt, long m0, long n0, int tid)
{
#pragma unroll
    for (int i = 0; i < 2; i++) {
        int c = tid + i * 256;
        int row = c >> 2, c4 = (c & 3) << 2;
        unsigned dst = sA + (unsigned)(row * 20 + c4) * 4u;
        const float* src = A + (m0 + row) * KP_ + kt * 16 + c4;
        asm volatile("cp.async.cg.shared.global [%0], [%1], 16;"
                     :: "r"(dst), "l"(src));
    }
#pragma unroll
    for (int i = 0; i < 2; i++) {
        int c = tid + i * 256;
        int row = c >> 5, c4 = (c & 31) << 2;
        unsigned dst = sB + (unsigned)(row * 136 + c4) * 4u;
        const float* src = Bw + (long)(kt * 16 + row) * G4 + n0 + c4;
        asm volatile("cp.async.cg.shared.global [%0], [%1], 16;"
                     :: "r"(dst), "l"(src));
    }
    asm volatile("cp.async.commit_group;");
}

__device__ __forceinline__ void pre_compute(
    const float* As, const float* Bs, float acc[4][4][4],
    int wr, int wc, int g, int t4)
{
#pragma unroll
    for (int ks = 0; ks < 2; ks++) {
        int k0 = ks * 8;
        unsigned af[4][4], bf[4][2];
#pragma unroll
        for (int mi = 0; mi < 4; mi++) {
            int rb = wr * 64 + mi * 16;
            af[mi][0] = __float_as_uint(As[(rb + g    ) * 20 + k0 + t4    ]);
            af[mi][1] = __float_as_uint(As[(rb + g + 8) * 20 + k0 + t4    ]);
            af[mi][2] = __float_as_uint(As[(rb + g    ) * 20 + k0 + t4 + 4]);
            af[mi][3] = __float_as_uint(As[(rb + g + 8) * 20 + k0 + t4 + 4]);
        }
#pragma unroll
        for (int ni = 0; ni < 4; ni++) {
            int cb = wc * 32 + ni * 8;
            bf[ni][0] = __float_as_uint(Bs[(k0 + t4    ) * 136 + cb + g]);
            bf[ni][1] = __float_as_uint(Bs[(k0 + t4 + 4) * 136 + cb + g]);
        }
#pragma unroll
        for (int mi = 0; mi < 4; mi++)
#pragma unroll
            for (int ni = 0; ni < 4; ni++)
                asm volatile(
                    "mma.sync.aligned.m16n8k8.row.col.f32.tf32.tf32.f32 "
                    "{%0,%1,%2,%3},{%4,%5,%6,%7},{%8,%9},{%0,%1,%2,%3};"
                    : "+f"(acc[mi][ni][0]), "+f"(acc[mi][ni][1]),
                      "+f"(acc[mi][ni][2]), "+f"(acc[mi][ni][3])
                    : "r"(af[mi][0]), "r"(af[mi][1]), "r"(af[mi][2]), "r"(af[mi][3]),
                      "r"(bf[ni][0]), "r"(bf[ni][1]));
    }
}

__global__ __launch_bounds__(256) void k_precompute2(
    const float* __restrict__ b0, const float* __restrict__ b1,
    const float* __restrict__ b2, const float* __restrict__ b3)
{
    extern __shared__ float smem[];
    float* As = smem;
    float* Bs = smem + NSTAGE * PRE_A_STAGE;
    unsigned sAb = (unsigned)__cvta_generic_to_shared(As);
    unsigned sBb = (unsigned)__cvta_generic_to_shared(Bs);

    int tid = threadIdx.x, lane = tid & 31, wid = tid >> 5;
    int wr = wid >> 2, wc = wid & 3, g = lane >> 2, t4 = lane & 3;
    int l = blockIdx.z;
    long n0 = (long)blockIdx.x * 128, m0 = (long)blockIdx.y * 128;
    const float* A  = g_xt + (long)(l >> 1) * BT * KP_;
    const float* Bw = g_wt + (long)l * KP_ * G4;
    const float* bb = (l == 0) ? b0 : (l == 1) ? b1 : (l == 2) ? b2 : b3;

    float acc[4][4][4];
#pragma unroll
    for (int mi = 0; mi < 4; mi++)
#pragma unroll
        for (int ni = 0; ni < 4; ni++)
#pragma unroll
            for (int k = 0; k < 4; k++) acc[mi][ni][k] = 0.f;

#pragma unroll
    for (int p = 0; p < NSTAGE - 1; p++)
        pre_issue(sAb + p * PRE_A_STAGE * 4, sBb + p * PRE_B_STAGE * 4,
                  A, Bw, p, m0, n0, tid);

    for (int kt = 0; kt < KT_PRE; kt++) {
        asm volatile("cp.async.wait_group %0;" :: "n"(NSTAGE - 2));
        __syncthreads();
        int stg = kt & (NSTAGE - 1);
        pre_compute(As + stg * PRE_A_STAGE, Bs + stg * PRE_B_STAGE,
                    acc, wr, wc, g, t4);
        int nk = kt + NSTAGE - 1;
        if (nk < KT_PRE)
            pre_issue(sAb + (nk & (NSTAGE - 1)) * PRE_A_STAGE * 4,
                      sBb + (nk & (NSTAGE - 1)) * PRE_B_STAGE * 4,
                      A, Bw, nk, m0, n0, tid);
        else
            asm volatile("cp.async.commit_group;");
    }

    float* out = g_pre + (long)l * BT * G4;
#pragma unroll
    for (int mi = 0; mi < 4; mi++)
#pragma unroll
        for (int ni = 0; ni < 4; ni++) {
            long col = n0 + wc * 32 + ni * 8 + t4 * 2;
            float bx = bb[col], by = bb[col + 1];
#pragma unroll
            for (int h = 0; h < 2; h++) {
                long row = m0 + wr * 64 + mi * 16 + g + h * 8;
                float2 v;
                v.x = acc[mi][ni][h * 2 + 0] + bx;
                v.y = acc[mi][ni][h * 2 + 1] + by;
                *(float2*)(out + row * G4 + col) = v;
            }
        }
}

// ===========================================================================
// Persistent recurrent kernel (128 blocks, 1/SM) — fp16 GEMM, fp32 accum.
// block = (l = bid>>5, nb = bid&31): 16 units x 4 gates, M=256, K=512.
// Wh in smem as packed m16n8k16 B-fragments. h streamed via cp.async in
// 8 stages of K=64 (4 mma-subtiles/stage). Cell state lives in registers
// for the whole 128-step loop; written to g_c once at the end.
// ===========================================================================
struct StepSmem {
    uint2  Wfrag[256][32];           // [kt*8 + wc*4 + ni][lane]  64 KB
    __half As[NSTAGE][256][72];      // 64 halves data + pad      144 KB
};
#define STEP_SMEM_BYTES sizeof(StepSmem)
#define AS_STAGE_BYTES (256 * 72 * 2)

__device__ __forceinline__ void issue_A64(unsigned as_base_b, const __half* hp,
                                          int s, int tid)
{
#pragma unroll
    for (int i = 0; i < 8; i++) {
        int c = tid + i * 256;               // 0..2047 chunks of 16B
        int row = c >> 3, ch = c & 7;
        unsigned dst = as_base_b + (unsigned)(row * 72 + ch * 8) * 2u;
        const __half* src = hp + row * 512 + s * 64 + ch * 8;
        asm volatile("cp.async.cg.shared.global [%0], [%1], 16;"
                     :: "r"(dst), "l"(src));
    }
    asm volatile("cp.async.commit_group;");
}

__device__ __forceinline__ void step_compute_stage(
    const StepSmem* s, int stg, int st, float acc[4][4][4],
    int wr, int wc, int g, int t4, int lane)
{
    const __half* As = &s->As[stg][0][0];
#pragma unroll
    for (int ks = 0; ks < 4; ks++) {
        int kh = ks * 16;
        unsigned af[4][4];
        uint2    bf[4];
#pragma unroll
        for (int mi = 0; mi < 4; mi++) {
            int r0 = (wr * 64 + mi * 16 + g) * 72;
            int r1 = r0 + 8 * 72;
            af[mi][0] = *(const unsigned*)(As + r0 + kh + 2 * t4);
            af[mi][1] = *(const unsigned*)(As + r1 + kh + 2 * t4);
            af[mi][2] = *(const unsigned*)(As + r0 + kh + 8 + 2 * t4);
            af[mi][3] = *(const unsigned*)(As + r1 + kh + 8 + 2 * t4);
        }
        int kt = st * 4 + ks;
#pragma unroll
        for (int ni = 0; ni < 4; ni++)
            bf[ni] = s->Wfrag[kt * 8 + wc * 4 + ni][lane];
#pragma unroll
        for (int mi = 0; mi < 4; mi++)
#pragma unroll
            for (int ni = 0; ni < 4; ni++)
                asm volatile(
                    "mma.sync.aligned.m16n8k16.row.col.f32.f16.f16.f32 "
                    "{%0,%1,%2,%3},{%4,%5,%6,%7},{%8,%9},{%0,%1,%2,%3};"
                    : "+f"(acc[mi][ni][0]), "+f"(acc[mi][ni][1]),
                      "+f"(acc[mi][ni][2]), "+f"(acc[mi][ni][3])
                    : "r"(af[mi][0]), "r"(af[mi][1]), "r"(af[mi][2]), "r"(af[mi][3]),
                      "r"(bf[ni].x), "r"(bf[ni].y));
    }
}

__global__ __launch_bounds__(256, 1) void k_step_persist()
{
    extern __shared__ char raw[];
    StepSmem* s = (StepSmem*)raw;
    int tid = threadIdx.x, lane = tid & 31, wid = tid >> 5;
    int wr = wid >> 1, wc = wid & 1, g = lane >> 2, t4 = lane & 3;
    int bid = blockIdx.x, l = bid >> 5, nb = bid & 31;
    const float* Wh = g_wh + (long)l * H_ * G4;

    // one-time: build fp16 B-fragments in smem (m16n8k16 layout).
    for (int f = wid; f < 256; f += 8) {
        int kt = f >> 3, rest = f & 7, wcf = rest >> 2, ni = rest & 3;
        int col = ni * H_ + nb * 16 + wcf * 8 + g;
        int k0  = kt * 16 + 2 * t4;
        float w0 = Wh[(long)(k0    ) * G4 + col];
        float w1 = Wh[(long)(k0 + 1) * G4 + col];
        float w2 = Wh[(long)(k0 + 8) * G4 + col];
        float w3 = Wh[(long)(k0 + 9) * G4 + col];
        __half2 p0 = __floats2half2_rn(w0, w1);
        __half2 p1 = __floats2half2_rn(w2, w3);
        uint2 v;
        v.x = *(unsigned*)&p0;
        v.y = *(unsigned*)&p1;
        s->Wfrag[f][lane] = v;
    }
    __syncthreads();

    const float* pre_l = g_pre + (long)l * BT * G4;
    unsigned as0 = (unsigned)__cvta_generic_to_shared(&s->As[0][0][0]);
    int u0 = nb * 16 + wc * 8 + t4 * 2;

    // cell state in registers for the whole time loop
    float creg[4][2][2];
#pragma unroll
    for (int mi = 0; mi < 4; mi++)
#pragma unroll
        for (int hh = 0; hh < 2; hh++) {
            creg[mi][hh][0] = 0.f;
            creg[mi][hh][1] = 0.f;
        }

    for (int t = 0; t < T_; t++) {
        const __half* hp = g_hh[t & 1] + l * B_ * H_;
        __half* hn = g_hh[(t + 1) & 1] + l * B_ * H_;
        int tl = (l & 1) ? (T_ - 1 - t) : t;

#pragma unroll
        for (int p = 0; p < NSTAGE - 1; p++)
            issue_A64(as0 + p * AS_STAGE_BYTES, hp, p, tid);

        // prefetch pre values into registers (hidden under the GEMM)
        float2 pr[4][2][4];
#pragma unroll
        for (int mi = 0; mi < 4; mi++)
#pragma unroll
            for (int hh = 0; hh < 2; hh++) {
                int  row = wr * 64 + mi * 16 + g + hh * 8;
                long pb  = ((long)row * T_ + tl) * G4;
#pragma unroll
                for (int gate = 0; gate < 4; gate++)
                    pr[mi][hh][gate] =
                        *(const float2*)(pre_l + pb + gate * H_ + u0);
            }

        float acc[4][4][4];
#pragma unroll
        for (int mi = 0; mi < 4; mi++)
#pragma unroll
            for (int ni = 0; ni < 4; ni++)
#pragma unroll
                for (int k = 0; k < 4; k++) acc[mi][ni][k] = 0.f;

        for (int st = 0; st < KT2; st++) {
            asm volatile("cp.async.wait_group %0;" :: "n"(NSTAGE - 2));
            __syncthreads();
            step_compute_stage(s, st & (NSTAGE - 1), st, acc, wr, wc, g, t4, lane);
            int nk = st + NSTAGE - 1;
            if (nk < KT2)
                issue_A64(as0 + (nk & (NSTAGE - 1)) * AS_STAGE_BYTES, hp, nk, tid);
            else
                asm volatile("cp.async.commit_group;");
        }

        // epilogue: gates + state update (c in registers, h2 stores)
#pragma unroll
        for (int mi = 0; mi < 4; mi++) {
#pragma unroll
            for (int hh = 0; hh < 2; hh++) {
                int row = wr * 64 + mi * 16 + g + hh * 8;
                float hv[2];
#pragma unroll
                for (int p = 0; p < 2; p++) {
                    int k = hh * 2 + p;
                    float pi = p ? pr[mi][hh][0].y : pr[mi][hh][0].x;
                    float pj = p ? pr[mi][hh][1].y : pr[mi][hh][1].x;
                    float pf = p ? pr[mi][hh][2].y : pr[mi][hh][2].x;
                    float po = p ? pr[mi][hh][3].y : pr[mi][hh][3].x;
                    float zi = acc[mi][0][k] + pi;
                    float zj = acc[mi][1][k] + pj;
                    float zf = acc[mi][2][k] + pf;
                    float zo = acc[mi][3][k] + po;
                    float co = creg[mi][hh][p];
                    float fg = 1.f / (1.f + __expf(-(zf + 1.f)));
                    float ig = 1.f / (1.f + __expf(-zi));
                    float og = 1.f / (1.f + __expf(-zo));
                    float cn = co * fg + ig * tanhf(zj);
                    creg[mi][hh][p] = cn;
                    hv[p] = tanhf(cn) * og;
                }
                *(__half2*)(hn + row * H_ + u0) = __floats2half2_rn(hv[0], hv[1]);
            }
        }

        // per-LSTM software barrier (32 blocks) — proven construct
        __threadfence();
        __syncthreads();
        if (tid == 0) {
            unsigned long long a = atomicAdd(&g_arrive[l], 1ULL) + 1ULL;
            unsigned long long want = (a + 31ULL) >> 5;
            if ((a & 31ULL) == 0ULL) {
                atomicAdd(&g_release[l], 1ULL);
            } else {
                while (*(volatile unsigned long long*)&g_release[l] < want) { }
            }
            __threadfence();
        }
        __syncthreads();
    }

    // write final cell state for the gather/MLP stage
    float* c_l = g_c + l * B_ * H_;
#pragma unroll
    for (int mi = 0; mi < 4; mi++)
#pragma unroll
        for (int hh = 0; hh < 2; hh++) {
            int row = wr * 64 + mi * 16 + g + hh * 8;
            *(float2*)(c_l + row * H_ + u0) =
                make_float2(creg[mi][hh][0], creg[mi][hh][1]);
        }
}

// ===========================================================================
// Tail: gather + MLP (tf32 2-stage GEMM, unchanged)
// ===========================================================================
struct GemmSmem {
    float As[2][128][20];
    float Bs[2][16][136];
};

__device__ __forceinline__ void stage_tiles(
    const float* __restrict__ A, long lda,
    const float* __restrict__ Bm, long ldb,
    int K, long m0, long n0, GemmSmem* s, int buf, int k0)
{
    int tid = threadIdx.x;
    {
        int r = tid >> 2;
        int c = (tid & 3) * 4;
#pragma unroll
        for (int i = 0; i < 2; i++) {
            int row = r + i * 64;
            const float* p = A + (m0 + row) * lda + (k0 + c);
            float4 v;
            if (k0 + c + 3 < K) {
                v = *(const float4*)p;
            } else {
                v.x = (k0 + c + 0 < K) ? p[0] : 0.f;
                v.y = (k0 + c + 1 < K) ? p[1] : 0.f;
                v.z = (k0 + c + 2 < K) ? p[2] : 0.f;
                v.w = (k0 + c + 3 < K) ? p[3] : 0.f;
            }
            s->As[buf][row][c + 0] = f2tf32(v.x);
            s->As[buf][row][c + 1] = f2tf32(v.y);
            s->As[buf][row][c + 2] = f2tf32(v.z);
            s->As[buf][row][c + 3] = f2tf32(v.w);
        }
    }
    {
        int r  = tid >> 4;
        int cb = (tid & 15) * 8;
#pragma unroll
        for (int j = 0; j < 2; j++) {
            int c = cb + j * 4;
            float4 v;
            if (k0 + r < K) {
                v = *(const float4*)(Bm + (long)(k0 + r) * ldb + n0 + c);
            } else {
                v.x = v.y = v.z = v.w = 0.f;
            }
            s->Bs[buf][r][c + 0] = f2tf32(v.x);
            s->Bs[buf][r][c + 1] = f2tf32(v.y);
            s->Bs[buf][r][c + 2] = f2tf32(v.z);
            s->Bs[buf][r][c + 3] = f2tf32(v.w);
        }
    }
}

__device__ __forceinline__ void gemm_main(
    const float* __restrict__ A, long lda,
    const float* __restrict__ Bm, long ldb,
    int K, long m0, long n0, GemmSmem* s, float acc[4][4][4])
{
    int lane = threadIdx.x & 31, wid = threadIdx.x >> 5;
    int wr = wid >> 2, wc = wid & 3, g = lane >> 2, t4 = lane & 3;
#pragma unroll
    for (int mi = 0; mi < 4; mi++)
#pragma unroll
        for (int ni = 0; ni < 4; ni++)
#pragma unroll
            for (int k = 0; k < 4; k++) acc[mi][ni][k] = 0.f;

    int nkt = (K + 15) >> 4;
    stage_tiles(A, lda, Bm, ldb, K, m0, n0, s, 0, 0);
    __syncthreads();
    for (int kt = 0; kt < nkt; kt++) {
        pre_compute(&s->As[kt & 1][0][0], &s->Bs[kt & 1][0][0], acc, wr, wc, g, t4);
        if (kt + 1 < nkt)
            stage_tiles(A, lda, Bm, ldb, K, m0, n0, s, (kt + 1) & 1, (kt + 1) * 16);
        __syncthreads();
    }
}

__global__ void k_gather()
{
    int idx = blockIdx.x * 256 + threadIdx.x;
    if (idx < B_ * G4) {
        int b = idx >> 11, kk = idx & 2047;
        int l = kk >> 9, gg = kk & 511;
        g_rnn[idx] = g_c[(long)l * B_ * H_ + (long)b * H_ + gg];
    }
}

__global__ __launch_bounds__(256) void k_dense(
    int a_sel, int K, const float* __restrict__ W, int N,
    const float* __restrict__ bias, int o_sel)
{
    long n0 = (long)blockIdx.x * 128, m0 = (long)blockIdx.y * 128;
    const float* A = (a_sel == 0) ? g_rnn : g_act[a_sel - 1];
    float* out = g_act[o_sel];
    __shared__ GemmSmem s;
    float acc[4][4][4];
    gemm_main(A, (a_sel == 0) ? G4 : F_, W, N, K, m0, n0, &s, acc);

    int lane = threadIdx.x & 31, wid = threadIdx.x >> 5;
    int wr = wid >> 2, wc = wid & 3, g = lane >> 2, t4 = lane & 3;
#pragma unroll
    for (int mi = 0; mi < 4; mi++)
#pragma unroll
        for (int ni = 0; ni < 4; ni++) {
            long col = n0 + wc * 32 + ni * 8 + t4 * 2;
            float bx = bias[col], by = bias[col + 1];
#pragma unroll
            for (int h = 0; h < 2; h++) {
                long row = m0 + wr * 64 + mi * 16 + g + h * 8;
                float2 v;
                v.x = tanhf(acc[mi][ni][h * 2 + 0] + bx);
                v.y = tanhf(acc[mi][ni][h * 2 + 1] + by);
                *(float2*)(out + row * (long)N + col) = v;
            }
        }
}

__global__ void k_logits(const float* __restrict__ W4,
                         const float* __restrict__ b4, float* __restrict__ out)
{
    int b = blockIdx.x, tid = threadIdx.x;
    const float* A = g_act[2] + (long)b * F_;
    float s0 = 0.f, s1 = 0.f, s2 = 0.f;
    for (int k = tid; k < F_; k += 128) {
        float a = A[k];
        s0 += a * W4[k * 3 + 0];
        s1 += a * W4[k * 3 + 1];
        s2 += a * W4[k * 3 + 2];
    }
#pragma unroll
    for (int off = 16; off; off >>= 1) {
        s0 += __shfl_down_sync(0xffffffffu, s0, off);
        s1 += __shfl_down_sync(0xffffffffu, s1, off);
        s2 += __shfl_down_sync(0xffffffffu, s2, off);
    }
    __shared__ float red[3][4];
    if ((tid & 31) == 0) {
        red[0][tid >> 5] = s0; red[1][tid >> 5] = s1; red[2][tid >> 5] = s2;
    }
    __syncthreads();
    if (tid == 0) {
        out[b * 3 + 0] = red[0][0] + red[0][1] + red[0][2] + red[0][3] + b4[0];
        out[b * 3 + 1] = red[1][0] + red[1][1] + red[1][2] + red[1][3] + b4[1];
        out[b * 3 + 2] = red[2][0] + red[2][1] + red[2][2] + red[2][3] + b4[2];
    }
}

// ---------------------------------------------------------------------------
// kernel_launch
// ---------------------------------------------------------------------------
extern "C" void kernel_launch(void* const* d_in, const int* in_sizes, int n_in,
                              void* d_out, int out_size)
{
    (void)in_sizes; (void)n_in; (void)out_size;
    const float* prem   = (const float*)d_in[0];
    const float* hyp    = (const float*)d_in[1];
    const float* W_fw_p = (const float*)d_in[2];
    const float* b_fw_p = (const float*)d_in[3];
    const float* W_bw_p = (const float*)d_in[4];
    const float* b_bw_p = (const float*)d_in[5];
    const float* W_fw_h = (const float*)d_in[6];
    const float* b_fw_h = (const float*)d_in[7];
    const float* W_bw_h = (const float*)d_in[8];
    const float* b_bw_h = (const float*)d_in[9];
    const float* W1 = (const float*)d_in[10];
    const float* b1 = (const float*)d_in[11];
    const float* W2 = (const float*)d_in[12];
    const float* b2 = (const float*)d_in[13];
    const float* W3 = (const float*)d_in[14];
    const float* b3 = (const float*)d_in[15];
    const float* W4 = (const float*)d_in[16];
    const float* b4 = (const float*)d_in[17];
    float* out = (float*)d_out;

    cudaFuncSetAttribute(k_step_persist,
                         cudaFuncAttributeMaxDynamicSharedMemorySize,
                         (int)STEP_SMEM_BYTES);
    cudaFuncSetAttribute(k_precompute2,
                         cudaFuncAttributeMaxDynamicSharedMemorySize,
                         (int)PRE_SMEM_BYTES);

    // Launch order matters for ncu (capture lands on launch index 3 = step).
    int nz = NL * B_ * H_;
    k_zero<<<(nz + 255) / 256, 256>>>();                              // 0

    long nx = 2L * BT * KP_;
    k_prep_all<<<(int)((nx + 255) / 256), 256>>>(
        prem, hyp, W_fw_p, W_bw_p, W_fw_h, W_bw_h);                   // 1

    k_precompute2<<<dim3(16, 256, 4), 256, PRE_SMEM_BYTES>>>(
        b_fw_p, b_bw_p, b_fw_h, b_bw_h);                              // 2

    k_step_persist<<<128, 256, STEP_SMEM_BYTES>>>();                  // 3

    k_gather<<<(B_ * G4 + 255) / 256, 256>>>();                       // 4

    k_dense<<<dim3(8, 2), 256>>>(0, G4, W1, F_, b1, 0);               // 5
    k_dense<<<dim3(8, 2), 256>>>(1, F_, W2, F_, b2, 1);               // 6
    k_dense<<<dim3(8, 2), 256>>>(2, F_, W3, F_, b3, 2);               // 7

    k_logits<<<B_, 128>>>(W4, b4, out);                               // 8
}

// round 12
// speedup vs baseline: 2.5651x; 1.0333x over previous
#include <cuda_runtime.h>
#include <cuda_fp16.h>
#include <math.h>

// Problem constants
#define B_  256
#define T_  128
#define E_  300
#define H_  512
#define G4  2048          // 4*H
#define F_  1024
#define NL  4
#define BT  32768         // B*T
#define KP_ 304           // E padded to 16
#define KT_PRE 19         // 304/16
#define KT2  8            // recurrent: 8 stages of K=64
#define NSTAGE 4

// ---------------------------------------------------------------------------
// Device scratch (static; no allocations anywhere)
// ---------------------------------------------------------------------------
__device__ float g_pre[268435456];            // [4][B*T][G4] = 1.07 GB
__device__ float g_xt [2 * BT * KP_];         // tf32-rounded, zero-padded inputs
__device__ float g_wt [NL * KP_ * G4];        // tf32-rounded, padded input weights
__device__ float g_wh [NL * H_  * G4];        // RAW fp32 recurrent weights
__device__ __align__(256) __half g_hh[2][NL * B_ * H_];  // fp16 hidden ping-pong
__device__ float g_c  [NL * B_ * H_];         // cell state (final only)
__device__ float g_rnn[B_ * G4];              // concat of final c's
__device__ float g_act[3][B_ * F_];           // MLP activations
__device__ unsigned long long g_arrive [NL];
__device__ unsigned long long g_release[NL];

__device__ __forceinline__ float f2tf32(float x) {
    unsigned u;
    asm("cvt.rna.tf32.f32 %0, %1;" : "=r"(u) : "f"(x));
    return __uint_as_float(u);
}

// ===========================================================================
// k_zero: zero initial states (per replay)
// ===========================================================================
__global__ void k_zero()
{
    int idx = blockIdx.x * 256 + threadIdx.x;
    if (idx < NL * B_ * H_) {
        g_hh[0][idx] = __float2half(0.f);
        g_hh[1][idx] = __float2half(0.f);
    }
}

// ===========================================================================
// k_prep_all: tf32 rounding for precompute operands; raw copy of Wh.
// ===========================================================================
__global__ void k_prep_all(
    const float* __restrict__ prem, const float* __restrict__ hyp,
    const float* __restrict__ W0, const float* __restrict__ W1,
    const float* __restrict__ W2, const float* __restrict__ W3)
{
    long idx = (long)blockIdx.x * 256 + threadIdx.x;

    if (idx < 2L * BT * KP_) {
        int which = (int)(idx / ((long)BT * KP_));
        long rem  = idx - (long)which * BT * KP_;
        int row = (int)(rem / KP_), col = (int)(rem - (long)row * KP_);
        const float* x = which ? hyp : prem;
        g_xt[idx] = (col < E_) ? f2tf32(x[(long)row * E_ + col]) : 0.f;
    }
    if (idx < (long)NL * KP_ * G4) {
        int l = (int)(idx / ((long)KP_ * G4));
        long rem = idx - (long)l * KP_ * G4;
        int r = (int)(rem / G4), c = (int)(rem - (long)r * G4);
        const float* W = (l == 0) ? W0 : (l == 1) ? W1 : (l == 2) ? W2 : W3;
        g_wt[idx] = (r < E_) ? f2tf32(W[(long)r * G4 + c]) : 0.f;
    }
    if (idx < (long)NL * H_ * G4) {
        int l = (int)(idx / ((long)H_ * G4));
        long rem = idx - (long)l * H_ * G4;
        int r = (int)(rem / G4), c = (int)(rem - (long)r * G4);
        const float* W = (l == 0) ? W0 : (l == 1) ? W1 : (l == 2) ? W2 : W3;
        g_wh[idx] = W[(long)(E_ + r) * G4 + c];   // raw; fp16-rounded in-kernel
    }
}

// ===========================================================================
// Precompute GEMM (tf32, unchanged): g_pre[l] = Xt @ Wt_l + b_l
// ===========================================================================
#define PRE_A_STAGE (128 * 20)
#define PRE_B_STAGE (16 * 136)
#define PRE_SMEM_BYTES ((NSTAGE * PRE_A_STAGE + NSTAGE * PRE_B_STAGE) * 4)

__device__ __forceinline__ void pre_issue(
    unsigned sA, unsigned sB, const float* __restrict__ A,
    const float* __restrict__ Bw, int kt, long m0, long n0, int tid)
{
#pragma unroll
    for (int i = 0; i < 2; i++) {
        int c = tid + i * 256;
        int row = c >> 2, c4 = (c & 3) << 2;
        unsigned dst = sA + (unsigned)(row * 20 + c4) * 4u;
        const float* src = A + (m0 + row) * KP_ + kt * 16 + c4;
        asm volatile("cp.async.cg.shared.global [%0], [%1], 16;"
                     :: "r"(dst), "l"(src));
    }
#pragma unroll
    for (int i = 0; i < 2; i++) {
        int c = tid + i * 256;
        int row = c >> 5, c4 = (c & 31) << 2;
        unsigned dst = sB + (unsigned)(row * 136 + c4) * 4u;
        const float* src = Bw + (long)(kt * 16 + row) * G4 + n0 + c4;
        asm volatile("cp.async.cg.shared.global [%0], [%1], 16;"
                     :: "r"(dst), "l"(src));
    }
    asm volatile("cp.async.commit_group;");
}

__device__ __forceinline__ void pre_compute(
    const float* As, const float* Bs, float acc[4][4][4],
    int wr, int wc, int g, int t4)
{
#pragma unroll
    for (int ks = 0; ks < 2; ks++) {
        int k0 = ks * 8;
        unsigned af[4][4], bf[4][2];
#pragma unroll
        for (int mi = 0; mi < 4; mi++) {
            int rb = wr * 64 + mi * 16;
            af[mi][0] = __float_as_uint(As[(rb + g    ) * 20 + k0 + t4    ]);
            af[mi][1] = __float_as_uint(As[(rb + g + 8) * 20 + k0 + t4    ]);
            af[mi][2] = __float_as_uint(As[(rb + g    ) * 20 + k0 + t4 + 4]);
            af[mi][3] = __float_as_uint(As[(rb + g + 8) * 20 + k0 + t4 + 4]);
        }
#pragma unroll
        for (int ni = 0; ni < 4; ni++) {
            int cb = wc * 32 + ni * 8;
            bf[ni][0] = __float_as_uint(Bs[(k0 + t4    ) * 136 + cb + g]);
            bf[ni][1] = __float_as_uint(Bs[(k0 + t4 + 4) * 136 + cb + g]);
        }
#pragma unroll
        for (int mi = 0; mi < 4; mi++)
#pragma unroll
            for (int ni = 0; ni < 4; ni++)
                asm volatile(
                    "mma.sync.aligned.m16n8k8.row.col.f32.tf32.tf32.f32 "
                    "{%0,%1,%2,%3},{%4,%5,%6,%7},{%8,%9},{%0,%1,%2,%3};"
                    : "+f"(acc[mi][ni][0]), "+f"(acc[mi][ni][1]),
                      "+f"(acc[mi][ni][2]), "+f"(acc[mi][ni][3])
                    : "r"(af[mi][0]), "r"(af[mi][1]), "r"(af[mi][2]), "r"(af[mi][3]),
                      "r"(bf[ni][0]), "r"(bf[ni][1]));
    }
}

__global__ __launch_bounds__(256) void k_precompute2(
    const float* __restrict__ b0, const float* __restrict__ b1,
    const float* __restrict__ b2, const float* __restrict__ b3)
{
    extern __shared__ float smem[];
    float* As = smem;
    float* Bs = smem + NSTAGE * PRE_A_STAGE;
    unsigned sAb = (unsigned)__cvta_generic_to_shared(As);
    unsigned sBb = (unsigned)__cvta_generic_to_shared(Bs);

    int tid = threadIdx.x, lane = tid & 31, wid = tid >> 5;
    int wr = wid >> 2, wc = wid & 3, g = lane >> 2, t4 = lane & 3;
    int l = blockIdx.z;
    long n0 = (long)blockIdx.x * 128, m0 = (long)blockIdx.y * 128;
    const float* A  = g_xt + (long)(l >> 1) * BT * KP_;
    const float* Bw = g_wt + (long)l * KP_ * G4;
    const float* bb = (l == 0) ? b0 : (l == 1) ? b1 : (l == 2) ? b2 : b3;

    float acc[4][4][4];
#pragma unroll
    for (int mi = 0; mi < 4; mi++)
#pragma unroll
        for (int ni = 0; ni < 4; ni++)
#pragma unroll
            for (int k = 0; k < 4; k++) acc[mi][ni][k] = 0.f;

#pragma unroll
    for (int p = 0; p < NSTAGE - 1; p++)
        pre_issue(sAb + p * PRE_A_STAGE * 4, sBb + p * PRE_B_STAGE * 4,
                  A, Bw, p, m0, n0, tid);

    for (int kt = 0; kt < KT_PRE; kt++) {
        asm volatile("cp.async.wait_group %0;" :: "n"(NSTAGE - 2));
        __syncthreads();
        int stg = kt & (NSTAGE - 1);
        pre_compute(As + stg * PRE_A_STAGE, Bs + stg * PRE_B_STAGE,
                    acc, wr, wc, g, t4);
        int nk = kt + NSTAGE - 1;
        if (nk < KT_PRE)
            pre_issue(sAb + (nk & (NSTAGE - 1)) * PRE_A_STAGE * 4,
                      sBb + (nk & (NSTAGE - 1)) * PRE_B_STAGE * 4,
                      A, Bw, nk, m0, n0, tid);
        else
            asm volatile("cp.async.commit_group;");
    }

    float* out = g_pre + (long)l * BT * G4;
#pragma unroll
    for (int mi = 0; mi < 4; mi++)
#pragma unroll
        for (int ni = 0; ni < 4; ni++) {
            long col = n0 + wc * 32 + ni * 8 + t4 * 2;
            float bx = bb[col], by = bb[col + 1];
#pragma unroll
            for (int h = 0; h < 2; h++) {
                long row = m0 + wr * 64 + mi * 16 + g + h * 8;
                float2 v;
                v.x = acc[mi][ni][h * 2 + 0] + bx;
                v.y = acc[mi][ni][h * 2 + 1] + by;
                *(float2*)(out + row * G4 + col) = v;
            }
        }
}

// ===========================================================================
// Persistent recurrent kernel (128 blocks, 1/SM, 512 threads) — fp16 GEMM.
// block = (l = bid>>5, nb = bid&31): 16 units x 4 gates, M=256, K=512.
// 16 warps: wr = wid>>1 (8 M-strips of 32 rows), wc = wid&1 (2 N-strips).
// Wh in smem as packed m16n8k16 B-fragments. h streamed via cp.async in
// 8 stages of K=64 (4 mma-subtiles/stage). Cell state in registers.
// ===========================================================================
#define STEP_THREADS 512

struct StepSmem {
    uint2  Wfrag[256][32];           // [kt*8 + wc*4 + ni][lane]  64 KB
    __half As[NSTAGE][256][72];      // 64 halves data + pad      144 KB
};
#define STEP_SMEM_BYTES sizeof(StepSmem)
#define AS_STAGE_BYTES (256 * 72 * 2)

__device__ __forceinline__ void issue_A64(unsigned as_base_b, const __half* hp,
                                          int s, int tid)
{
#pragma unroll
    for (int i = 0; i < 4; i++) {
        int c = tid + i * STEP_THREADS;      // 0..2047 chunks of 16B
        int row = c >> 3, ch = c & 7;
        unsigned dst = as_base_b + (unsigned)(row * 72 + ch * 8) * 2u;
        const __half* src = hp + row * 512 + s * 64 + ch * 8;
        asm volatile("cp.async.cg.shared.global [%0], [%1], 16;"
                     :: "r"(dst), "l"(src));
    }
    asm volatile("cp.async.commit_group;");
}

__device__ __forceinline__ void step_compute_stage(
    const StepSmem* s, int stg, int st, float acc[2][4][4],
    int wr, int wc, int g, int t4, int lane)
{
    const __half* As = &s->As[stg][0][0];
#pragma unroll
    for (int ks = 0; ks < 4; ks++) {
        int kh = ks * 16;
        unsigned af[2][4];
        uint2    bf[4];
#pragma unroll
        for (int mi = 0; mi < 2; mi++) {
            int r0 = (wr * 32 + mi * 16 + g) * 72;
            int r1 = r0 + 8 * 72;
            af[mi][0] = *(const unsigned*)(As + r0 + kh + 2 * t4);
            af[mi][1] = *(const unsigned*)(As + r1 + kh + 2 * t4);
            af[mi][2] = *(const unsigned*)(As + r0 + kh + 8 + 2 * t4);
            af[mi][3] = *(const unsigned*)(As + r1 + kh + 8 + 2 * t4);
        }
        int kt = st * 4 + ks;
#pragma unroll
        for (int ni = 0; ni < 4; ni++)
            bf[ni] = s->Wfrag[kt * 8 + wc * 4 + ni][lane];
#pragma unroll
        for (int mi = 0; mi < 2; mi++)
#pragma unroll
            for (int ni = 0; ni < 4; ni++)
                asm volatile(
                    "mma.sync.aligned.m16n8k16.row.col.f32.f16.f16.f32 "
                    "{%0,%1,%2,%3},{%4,%5,%6,%7},{%8,%9},{%0,%1,%2,%3};"
                    : "+f"(acc[mi][ni][0]), "+f"(acc[mi][ni][1]),
                      "+f"(acc[mi][ni][2]), "+f"(acc[mi][ni][3])
                    : "r"(af[mi][0]), "r"(af[mi][1]), "r"(af[mi][2]), "r"(af[mi][3]),
                      "r"(bf[ni].x), "r"(bf[ni].y));
    }
}

__global__ __launch_bounds__(STEP_THREADS, 1) void k_step_persist()
{
    extern __shared__ char raw[];
    StepSmem* s = (StepSmem*)raw;
    int tid = threadIdx.x, lane = tid & 31, wid = tid >> 5;
    int wr = wid >> 1, wc = wid & 1, g = lane >> 2, t4 = lane & 3;
    int bid = blockIdx.x, l = bid >> 5, nb = bid & 31;
    const float* Wh = g_wh + (long)l * H_ * G4;

    // one-time: build fp16 B-fragments in smem (m16n8k16 layout).
    for (int f = wid; f < 256; f += 16) {
        int kt = f >> 3, rest = f & 7, wcf = rest >> 2, ni = rest & 3;
        int col = ni * H_ + nb * 16 + wcf * 8 + g;
        int k0  = kt * 16 + 2 * t4;
        float w0 = Wh[(long)(k0    ) * G4 + col];
        float w1 = Wh[(long)(k0 + 1) * G4 + col];
        float w2 = Wh[(long)(k0 + 8) * G4 + col];
        float w3 = Wh[(long)(k0 + 9) * G4 + col];
        __half2 p0 = __floats2half2_rn(w0, w1);
        __half2 p1 = __floats2half2_rn(w2, w3);
        uint2 v;
        v.x = *(unsigned*)&p0;
        v.y = *(unsigned*)&p1;
        s->Wfrag[f][lane] = v;
    }
    __syncthreads();

    const float* pre_l = g_pre + (long)l * BT * G4;
    unsigned as0 = (unsigned)__cvta_generic_to_shared(&s->As[0][0][0]);
    int u0 = nb * 16 + wc * 8 + t4 * 2;

    // cell state in registers for the whole time loop
    float creg[2][2][2];
#pragma unroll
    for (int mi = 0; mi < 2; mi++)
#pragma unroll
        for (int hh = 0; hh < 2; hh++) {
            creg[mi][hh][0] = 0.f;
            creg[mi][hh][1] = 0.f;
        }

    for (int t = 0; t < T_; t++) {
        const __half* hp = g_hh[t & 1] + l * B_ * H_;
        __half* hn = g_hh[(t + 1) & 1] + l * B_ * H_;
        int tl = (l & 1) ? (T_ - 1 - t) : t;

#pragma unroll
        for (int p = 0; p < NSTAGE - 1; p++)
            issue_A64(as0 + p * AS_STAGE_BYTES, hp, p, tid);

        // prefetch pre values into registers (hidden under the GEMM)
        float2 pr[2][2][4];
#pragma unroll
        for (int mi = 0; mi < 2; mi++)
#pragma unroll
            for (int hh = 0; hh < 2; hh++) {
                int  row = wr * 32 + mi * 16 + g + hh * 8;
                long pb  = ((long)row * T_ + tl) * G4;
#pragma unroll
                for (int gate = 0; gate < 4; gate++)
                    pr[mi][hh][gate] =
                        *(const float2*)(pre_l + pb + gate * H_ + u0);
            }

        float acc[2][4][4];
#pragma unroll
        for (int mi = 0; mi < 2; mi++)
#pragma unroll
            for (int ni = 0; ni < 4; ni++)
#pragma unroll
                for (int k = 0; k < 4; k++) acc[mi][ni][k] = 0.f;

        for (int st = 0; st < KT2; st++) {
            asm volatile("cp.async.wait_group %0;" :: "n"(NSTAGE - 2));
            __syncthreads();
            step_compute_stage(s, st & (NSTAGE - 1), st, acc, wr, wc, g, t4, lane);
            int nk = st + NSTAGE - 1;
            if (nk < KT2)
                issue_A64(as0 + (nk & (NSTAGE - 1)) * AS_STAGE_BYTES, hp, nk, tid);
            else
                asm volatile("cp.async.commit_group;");
        }

        // epilogue: gates + state update (c in registers, h2 stores)
#pragma unroll
        for (int mi = 0; mi < 2; mi++) {
#pragma unroll
            for (int hh = 0; hh < 2; hh++) {
                int row = wr * 32 + mi * 16 + g + hh * 8;
                float hv[2];
#pragma unroll
                for (int p = 0; p < 2; p++) {
                    int k = hh * 2 + p;
                    float pi = p ? pr[mi][hh][0].y : pr[mi][hh][0].x;
                    float pj = p ? pr[mi][hh][1].y : pr[mi][hh][1].x;
                    float pf = p ? pr[mi][hh][2].y : pr[mi][hh][2].x;
                    float po = p ? pr[mi][hh][3].y : pr[mi][hh][3].x;
                    float zi = acc[mi][0][k] + pi;
                    float zj = acc[mi][1][k] + pj;
                    float zf = acc[mi][2][k] + pf;
                    float zo = acc[mi][3][k] + po;
                    float co = creg[mi][hh][p];
                    float fg = 1.f / (1.f + __expf(-(zf + 1.f)));
                    float ig = 1.f / (1.f + __expf(-zi));
                    float og = 1.f / (1.f + __expf(-zo));
                    float cn = co * fg + ig * tanhf(zj);
                    creg[mi][hh][p] = cn;
                    hv[p] = tanhf(cn) * og;
                }
                *(__half2*)(hn + row * H_ + u0) = __floats2half2_rn(hv[0], hv[1]);
            }
        }

        // per-LSTM software barrier (32 blocks) — proven construct
        __threadfence();
        __syncthreads();
        if (tid == 0) {
            unsigned long long a = atomicAdd(&g_arrive[l], 1ULL) + 1ULL;
            unsigned long long want = (a + 31ULL) >> 5;
            if ((a & 31ULL) == 0ULL) {
                atomicAdd(&g_release[l], 1ULL);
            } else {
                while (*(volatile unsigned long long*)&g_release[l] < want) { }
            }
            __threadfence();
        }
        __syncthreads();
    }

    // write final cell state for the gather/MLP stage
    float* c_l = g_c + l * B_ * H_;
#pragma unroll
    for (int mi = 0; mi < 2; mi++)
#pragma unroll
        for (int hh = 0; hh < 2; hh++) {
            int row = wr * 32 + mi * 16 + g + hh * 8;
            *(float2*)(c_l + row * H_ + u0) =
                make_float2(creg[mi][hh][0], creg[mi][hh][1]);
        }
}

// ===========================================================================
// Tail: gather + MLP (tf32 2-stage GEMM, unchanged)
// ===========================================================================
struct GemmSmem {
    float As[2][128][20];
    float Bs[2][16][136];
};

__device__ __forceinline__ void stage_tiles(
    const float* __restrict__ A, long lda,
    const float* __restrict__ Bm, long ldb,
    int K, long m0, long n0, GemmSmem* s, int buf, int k0)
{
    int tid = threadIdx.x;
    {
        int r = tid >> 2;
        int c = (tid & 3) * 4;
#pragma unroll
        for (int i = 0; i < 2; i++) {
            int row = r + i * 64;
            const float* p = A + (m0 + row) * lda + (k0 + c);
            float4 v;
            if (k0 + c + 3 < K) {
                v = *(const float4*)p;
            } else {
                v.x = (k0 + c + 0 < K) ? p[0] : 0.f;
                v.y = (k0 + c + 1 < K) ? p[1] : 0.f;
                v.z = (k0 + c + 2 < K) ? p[2] : 0.f;
                v.w = (k0 + c + 3 < K) ? p[3] : 0.f;
            }
            s->As[buf][row][c + 0] = f2tf32(v.x);
            s->As[buf][row][c + 1] = f2tf32(v.y);
            s->As[buf][row][c + 2] = f2tf32(v.z);
            s->As[buf][row][c + 3] = f2tf32(v.w);
        }
    }
    {
        int r  = tid >> 4;
        int cb = (tid & 15) * 8;
#pragma unroll
        for (int j = 0; j < 2; j++) {
            int c = cb + j * 4;
            float4 v;
            if (k0 + r < K) {
                v = *(const float4*)(Bm + (long)(k0 + r) * ldb + n0 + c);
            } else {
                v.x = v.y = v.z = v.w = 0.f;
            }
            s->Bs[buf][r][c + 0] = f2tf32(v.x);
            s->Bs[buf][r][c + 1] = f2tf32(v.y);
            s->Bs[buf][r][c + 2] = f2tf32(v.z);
            s->Bs[buf][r][c + 3] = f2tf32(v.w);
        }
    }
}

__device__ __forceinline__ void gemm_main(
    const float* __restrict__ A, long lda,
    const float* __restrict__ Bm, long ldb,
    int K, long m0, long n0, GemmSmem* s, float acc[4][4][4])
{
    int lane = threadIdx.x & 31, wid = threadIdx.x >> 5;
    int wr = wid >> 2, wc = wid & 3, g = lane >> 2, t4 = lane & 3;
#pragma unroll
    for (int mi = 0; mi < 4; mi++)
#pragma unroll
        for (int ni = 0; ni < 4; ni++)
#pragma unroll
            for (int k = 0; k < 4; k++) acc[mi][ni][k] = 0.f;

    int nkt = (K + 15) >> 4;
    stage_tiles(A, lda, Bm, ldb, K, m0, n0, s, 0, 0);
    __syncthreads();
    for (int kt = 0; kt < nkt; kt++) {
        pre_compute(&s->As[kt & 1][0][0], &s->Bs[kt & 1][0][0], acc, wr, wc, g, t4);
        if (kt + 1 < nkt)
            stage_tiles(A, lda, Bm, ldb, K, m0, n0, s, (kt + 1) & 1, (kt + 1) * 16);
        __syncthreads();
    }
}

__global__ void k_gather()
{
    int idx = blockIdx.x * 256 + threadIdx.x;
    if (idx < B_ * G4) {
        int b = idx >> 11, kk = idx & 2047;
        int l = kk >> 9, gg = kk & 511;
        g_rnn[idx] = g_c[(long)l * B_ * H_ + (long)b * H_ + gg];
    }
}

__global__ __launch_bounds__(256) void k_dense(
    int a_sel, int K, const float* __restrict__ W, int N,
    const float* __restrict__ bias, int o_sel)
{
    long n0 = (long)blockIdx.x * 128, m0 = (long)blockIdx.y * 128;
    const float* A = (a_sel == 0) ? g_rnn : g_act[a_sel - 1];
    float* out = g_act[o_sel];
    __shared__ GemmSmem s;
    float acc[4][4][4];
    gemm_main(A, (a_sel == 0) ? G4 : F_, W, N, K, m0, n0, &s, acc);

    int lane = threadIdx.x & 31, wid = threadIdx.x >> 5;
    int wr = wid >> 2, wc = wid & 3, g = lane >> 2, t4 = lane & 3;
#pragma unroll
    for (int mi = 0; mi < 4; mi++)
#pragma unroll
        for (int ni = 0; ni < 4; ni++) {
            long col = n0 + wc * 32 + ni * 8 + t4 * 2;
            float bx = bias[col], by = bias[col + 1];
#pragma unroll
            for (int h = 0; h < 2; h++) {
                long row = m0 + wr * 64 + mi * 16 + g + h * 8;
                float2 v;
                v.x = tanhf(acc[mi][ni][h * 2 + 0] + bx);
                v.y = tanhf(acc[mi][ni][h * 2 + 1] + by);
                *(float2*)(out + row * (long)N + col) = v;
            }
        }
}

__global__ void k_logits(const float* __restrict__ W4,
                         const float* __restrict__ b4, float* __restrict__ out)
{
    int b = blockIdx.x, tid = threadIdx.x;
    const float* A = g_act[2] + (long)b * F_;
    float s0 = 0.f, s1 = 0.f, s2 = 0.f;
    for (int k = tid; k < F_; k += 128) {
        float a = A[k];
        s0 += a * W4[k * 3 + 0];
        s1 += a * W4[k * 3 + 1];
        s2 += a * W4[k * 3 + 2];
    }
#pragma unroll
    for (int off = 16; off; off >>= 1) {
        s0 += __shfl_down_sync(0xffffffffu, s0, off);
        s1 += __shfl_down_sync(0xffffffffu, s1, off);
        s2 += __shfl_down_sync(0xffffffffu, s2, off);
    }
    __shared__ float red[3][4];
    if ((tid & 31) == 0) {
        red[0][tid >> 5] = s0; red[1][tid >> 5] = s1; red[2][tid >> 5] = s2;
    }
    __syncthreads();
    if (tid == 0) {
        out[b * 3 + 0] = red[0][0] + red[0][1] + red[0][2] + red[0][3] + b4[0];
        out[b * 3 + 1] = red[1][0] + red[1][1] + red[1][2] + red[1][3] + b4[1];
        out[b * 3 + 2] = red[2][0] + red[2][1] + red[2][2] + red[2][3] + b4[2];
    }
}

// ---------------------------------------------------------------------------
// kernel_launch
// ---------------------------------------------------------------------------
extern "C" void kernel_launch(void* const* d_in, const int* in_sizes, int n_in,
                              void* d_out, int out_size)
{
    (void)in_sizes; (void)n_in; (void)out_size;
    const float* prem   = (const float*)d_in[0];
    const float* hyp    = (const float*)d_in[1];
    const float* W_fw_p = (const float*)d_in[2];
    const float* b_fw_p = (const float*)d_in[3];
    const float* W_bw_p = (const float*)d_in[4];
    const float* b_bw_p = (const float*)d_in[5];
    const float* W_fw_h = (const float*)d_in[6];
    const float* b_fw_h = (const float*)d_in[7];
    const float* W_bw_h = (const float*)d_in[8];
    const float* b_bw_h = (const float*)d_in[9];
    const float* W1 = (const float*)d_in[10];
    const float* b1 = (const float*)d_in[11];
    const float* W2 = (const float*)d_in[12];
    const float* b2 = (const float*)d_in[13];
    const float* W3 = (const float*)d_in[14];
    const float* b3 = (const float*)d_in[15];
    const float* W4 = (const float*)d_in[16];
    const float* b4 = (const float*)d_in[17];
    float* out = (float*)d_out;

    cudaFuncSetAttribute(k_step_persist,
                         cudaFuncAttributeMaxDynamicSharedMemorySize,
                         (int)STEP_SMEM_BYTES);
    cudaFuncSetAttribute(k_precompute2,
                         cudaFuncAttributeMaxDynamicSharedMemorySize,
                         (int)PRE_SMEM_BYTES);

    // Launch order matters for ncu (capture lands on launch index 3 = step).
    int nz = NL * B_ * H_;
    k_zero<<<(nz + 255) / 256, 256>>>();                              // 0

    long nx = 2L * BT * KP_;
    k_prep_all<<<(int)((nx + 255) / 256), 256>>>(
        prem, hyp, W_fw_p, W_bw_p, W_fw_h, W_bw_h);                   // 1

    k_precompute2<<<dim3(16, 256, 4), 256, PRE_SMEM_BYTES>>>(
        b_fw_p, b_bw_p, b_fw_h, b_bw_h);                              // 2

    k_step_persist<<<128, STEP_THREADS, STEP_SMEM_BYTES>>>();         // 3

    k_gather<<<(B_ * G4 + 255) / 256, 256>>>();                       // 4

    k_dense<<<dim3(8, 2), 256>>>(0, G4, W1, F_, b1, 0);               // 5
    k_dense<<<dim3(8, 2), 256>>>(1, F_, W2, F_, b2, 1);               // 6
    k_dense<<<dim3(8, 2), 256>>>(2, F_, W3, F_, b3, 2);               // 7

    k_logits<<<B_, 128>>>(W4, b4, out);                               // 8
}